// round 2
// baseline (speedup 1.0000x reference)
#include <cuda_runtime.h>
#include <cuda_bf16.h>
#include <cstdint>
#include <cmath>

// ---------------------------------------------------------------------------
// Problem constants (fixed shapes)
// ---------------------------------------------------------------------------
#define BB 2
#define TT 2048
#define NE 2048          // N_EMBED
#define NH 16            // N_HEAD
#define NKV 4            // N_KV_HEAD
#define HD 128           // HEAD_DIM
#define MROWS (BB*TT)    // 4096
#define KVDIM (NKV*HD)   // 512

// ---------------------------------------------------------------------------
// Scratch (static device globals; no allocations allowed)
// ---------------------------------------------------------------------------
__device__ float g_q[(size_t)MROWS * NE];       // x@Wq+bq
__device__ float g_k[(size_t)MROWS * KVDIM];    // x@Wk+bk
__device__ float g_v[(size_t)MROWS * KVDIM];    // x@Wv+bv
__device__ float g_o[(size_t)MROWS * NE];       // attention output [B,T,H*D]
__device__ __nv_bfloat16 g_qr[(size_t)BB * NH * TT * HD];   // rope(q) bf16 [B,H,T,D]
__device__ __nv_bfloat16 g_kr[(size_t)BB * NKV * TT * HD];  // rope(k) bf16 [B,KV,T,D]
__device__ float g_cos[TT * (HD/2)];
__device__ float g_sin[TT * (HD/2)];

// ---------------------------------------------------------------------------
// SGEMM: C[M,N] = A[M,K] @ B[K,N] + bias[N]   (all row-major, fp32)
// 128x128 block tile, BK=16, 256 threads, 8x8 per-thread micro-tile.
// M % 128 == 0, N % 128 == 0, K % 16 == 0 (true for all our shapes).
// ---------------------------------------------------------------------------
__device__ __forceinline__ void gemm_body(const float* __restrict__ A,
                                          const float* __restrict__ B,
                                          const float* __restrict__ bias,
                                          float* __restrict__ C,
                                          int M, int N, int K)
{
    __shared__ float As[16 * 128];   // transposed: As[k][m]
    __shared__ float Bs[16 * 128];   // Bs[k][n]

    const int tid = threadIdx.x;     // 0..255
    const int tx  = tid & 15;        // N micro index
    const int ty  = tid >> 4;        // M micro index
    const int m0  = blockIdx.y * 128;
    const int n0  = blockIdx.x * 128;

    float acc[8][8];
    #pragma unroll
    for (int i = 0; i < 8; i++)
        #pragma unroll
        for (int j = 0; j < 8; j++) acc[i][j] = 0.f;

    for (int k0 = 0; k0 < K; k0 += 16) {
        // load A tile (128 rows x 16 cols), store transposed
        #pragma unroll
        for (int s = 0; s < 2; s++) {
            int f   = tid * 2 + s;           // 0..511
            int row = f >> 2;                // 0..127
            int kq  = (f & 3) << 2;          // 0,4,8,12
            float4 av = *(const float4*)&A[(size_t)(m0 + row) * K + k0 + kq];
            As[(kq + 0) * 128 + row] = av.x;
            As[(kq + 1) * 128 + row] = av.y;
            As[(kq + 2) * 128 + row] = av.z;
            As[(kq + 3) * 128 + row] = av.w;
        }
        // load B tile (16 rows x 128 cols)
        #pragma unroll
        for (int s = 0; s < 2; s++) {
            int f   = tid * 2 + s;
            int row = f >> 5;                // 0..15
            int c4  = (f & 31) << 2;         // 0..124
            *(float4*)&Bs[row * 128 + c4] =
                *(const float4*)&B[(size_t)(k0 + row) * N + n0 + c4];
        }
        __syncthreads();

        #pragma unroll
        for (int k = 0; k < 16; k++) {
            float a[8], bv[8];
            *(float4*)&a[0]  = *(float4*)&As[k * 128 + ty * 4];
            *(float4*)&a[4]  = *(float4*)&As[k * 128 + 64 + ty * 4];
            *(float4*)&bv[0] = *(float4*)&Bs[k * 128 + tx * 4];
            *(float4*)&bv[4] = *(float4*)&Bs[k * 128 + 64 + tx * 4];
            #pragma unroll
            for (int i = 0; i < 8; i++)
                #pragma unroll
                for (int j = 0; j < 8; j++)
                    acc[i][j] += a[i] * bv[j];
        }
        __syncthreads();
    }

    // epilogue: add bias, store
    #pragma unroll
    for (int ih = 0; ih < 2; ih++) {
        #pragma unroll
        for (int i = 0; i < 4; i++) {
            int gm = m0 + ih * 64 + ty * 4 + i;
            #pragma unroll
            for (int jh = 0; jh < 2; jh++) {
                int gn = n0 + jh * 64 + tx * 4;
                float4 bv = *(const float4*)&bias[gn];
                float4 o;
                o.x = acc[ih * 4 + i][jh * 4 + 0] + bv.x;
                o.y = acc[ih * 4 + i][jh * 4 + 1] + bv.y;
                o.z = acc[ih * 4 + i][jh * 4 + 2] + bv.z;
                o.w = acc[ih * 4 + i][jh * 4 + 3] + bv.w;
                *(float4*)&C[(size_t)gm * N + gn] = o;
            }
        }
    }
}

__global__ void __launch_bounds__(256)
gemm_bias_kernel(const float* __restrict__ A, const float* __restrict__ B,
                 const float* __restrict__ bias, float* __restrict__ C,
                 int M, int N, int K)
{
    gemm_body(A, B, bias, C, M, N, K);
}

__global__ void __launch_bounds__(256)
gemm_kv_kernel(const float* __restrict__ A,
               const float* __restrict__ B0, const float* __restrict__ bias0, float* __restrict__ C0,
               const float* __restrict__ B1, const float* __restrict__ bias1, float* __restrict__ C1,
               int M, int N, int K)
{
    const float* B    = blockIdx.z ? B1    : B0;
    const float* bias = blockIdx.z ? bias1 : bias0;
    float*       C    = blockIdx.z ? C1    : C0;
    gemm_body(A, B, bias, C, M, N, K);
}

// ---------------------------------------------------------------------------
// RoPE table: angle = fp32(t) * fp32(double-precision freq), matching the
// reference's fp32 pipeline as closely as possible.
// ---------------------------------------------------------------------------
__global__ void __launch_bounds__(256)
rope_table_kernel(float* __restrict__ ct, float* __restrict__ st)
{
    int idx = blockIdx.x * 256 + threadIdx.x;
    if (idx >= TT * (HD/2)) return;
    int t = idx >> 6;
    int i = idx & 63;
    double fr = exp(-((double)(2 * i) / (double)NE) * log(10000.0));
    float ff = (float)fr;
    float ang = __fmul_rn((float)t, ff);
    float s, c;
    sincosf(ang, &s, &c);
    ct[idx] = c;
    st[idx] = s;
}

// rope + bf16 round for Q: [B,T,H,D] fp32 -> [B,H,T,D] bf16
__global__ void __launch_bounds__(256)
rope_q_kernel(const float* __restrict__ q, const float* __restrict__ ct,
              const float* __restrict__ st, __nv_bfloat16* __restrict__ qr)
{
    int idx = blockIdx.x * 256 + threadIdx.x;   // total BB*TT*NH*64
    int i = idx & 63;
    int h = (idx >> 6) & 15;
    int t = (idx >> 10) & 2047;
    int b = idx >> 21;
    size_t src = ((size_t)(b * TT + t)) * NE + h * HD + 2 * i;
    float xr = q[src], xi = q[src + 1];
    float c = ct[t * 64 + i], s = st[t * 64 + i];
    float orr = xr * c - xi * s;
    float oii = xr * s + xi * c;
    size_t dst = ((size_t)((b * NH + h) * TT + t)) * HD + 2 * i;
    qr[dst]     = __float2bfloat16(orr);
    qr[dst + 1] = __float2bfloat16(oii);
}

// rope + bf16 round for K: [B,T,KV,D] fp32 -> [B,KV,T,D] bf16
__global__ void __launch_bounds__(256)
rope_k_kernel(const float* __restrict__ k, const float* __restrict__ ct,
              const float* __restrict__ st, __nv_bfloat16* __restrict__ kr)
{
    int idx = blockIdx.x * 256 + threadIdx.x;   // total BB*TT*NKV*64
    int i = idx & 63;
    int h = (idx >> 6) & 3;
    int t = (idx >> 8) & 2047;
    int b = idx >> 19;
    size_t src = ((size_t)(b * TT + t)) * KVDIM + h * HD + 2 * i;
    float xr = k[src], xi = k[src + 1];
    float c = ct[t * 64 + i], s = st[t * 64 + i];
    float orr = xr * c - xi * s;
    float oii = xr * s + xi * c;
    size_t dst = ((size_t)((b * NKV + h) * TT + t)) * HD + 2 * i;
    kr[dst]     = __float2bfloat16(orr);
    kr[dst + 1] = __float2bfloat16(oii);
}

// ---------------------------------------------------------------------------
// Flash attention (causal, GQA). fp32 SIMT. BM=BN=64, 256 threads.
// attn = softmax(q@k^T) * 2048^-0.5;  o = attn @ v.
// smem: qs[64][128] | kst[128][65] (k transposed) | vs[64][128] | ss[64][68]
// ---------------------------------------------------------------------------
#define ATTN_SMEM_FLOATS (64*128 + 128*65 + 64*128 + 64*68)

__global__ void __launch_bounds__(256)
attn_kernel(const __nv_bfloat16* __restrict__ qr, const __nv_bfloat16* __restrict__ kr,
            const float* __restrict__ v, float* __restrict__ o)
{
    extern __shared__ float sm[];
    float* qs  = sm;                       // 8192
    float* kst = sm + 64 * 128;            // 8320 (stride 65)
    float* vs  = kst + 128 * 65;           // 8192
    float* ss  = vs + 64 * 128;            // 64*68 (stride 68)

    const int tid = threadIdx.x;
    const int mt = blockIdx.x, h = blockIdx.y, b = blockIdx.z;
    const int m0 = mt * 64;
    const int kv = h >> 2;                 // REPEAT = 4

    const __nv_bfloat16* qg = qr + ((size_t)(b * NH + h) * TT + m0) * HD;
    const __nv_bfloat16* kg = kr + ((size_t)(b * NKV + kv) * TT) * HD;
    const float*         vg = v  + ((size_t)b * TT) * KVDIM + kv * HD;

    // load q tile -> qs (fp32)
    for (int idx = tid; idx < 64 * 16; idx += 256) {
        int r  = idx >> 4;
        int d8 = (idx & 15) << 3;
        uint4 u = *(const uint4*)(qg + (size_t)r * HD + d8);
        const __nv_bfloat16* pb = (const __nv_bfloat16*)&u;
        #pragma unroll
        for (int j = 0; j < 8; j++)
            qs[r * 128 + d8 + j] = __bfloat162float(pb[j]);
    }

    float acc[32];
    #pragma unroll
    for (int j = 0; j < 32; j++) acc[j] = 0.f;
    float mrow = -1e30f, lrow = 0.f;

    const int r  = tid >> 2;   // row 0..63 (softmax/AV stage)
    const int cg = tid & 3;    // column group
    const int tx = tid & 15;   // score micro-tile N
    const int ty = tid >> 4;   // score micro-tile M

    const int ntile = mt + 1;  // causal: keys up to m0+63
    for (int jt = 0; jt < ntile; jt++) {
        const int kn = jt * 64;
        __syncthreads();  // previous tile fully consumed (and q loaded, 1st iter)

        // load k tile transposed: kst[d][n]
        for (int idx = tid; idx < 64 * 16; idx += 256) {
            int n  = idx >> 4;
            int d8 = (idx & 15) << 3;
            uint4 u = *(const uint4*)(kg + (size_t)(kn + n) * HD + d8);
            const __nv_bfloat16* pb = (const __nv_bfloat16*)&u;
            #pragma unroll
            for (int j = 0; j < 8; j++)
                kst[(d8 + j) * 65 + n] = __bfloat162float(pb[j]);
        }
        // load v tile: vs[n][c]
        for (int idx = tid; idx < 64 * 32; idx += 256) {
            int n  = idx >> 5;
            int c4 = (idx & 31) << 2;
            *(float4*)&vs[n * 128 + c4] =
                *(const float4*)(vg + (size_t)(kn + n) * KVDIM + c4);
        }
        __syncthreads();

        // scores: s = q @ k^T  (64x64x128), 4x4 micro-tile per thread
        float sacc[4][4];
        #pragma unroll
        for (int i = 0; i < 4; i++)
            #pragma unroll
            for (int j = 0; j < 4; j++) sacc[i][j] = 0.f;

        #pragma unroll 4
        for (int d = 0; d < 128; d++) {
            float a0 = qs[(ty * 4 + 0) * 128 + d];
            float a1 = qs[(ty * 4 + 1) * 128 + d];
            float a2 = qs[(ty * 4 + 2) * 128 + d];
            float a3 = qs[(ty * 4 + 3) * 128 + d];
            float b0 = kst[d * 65 + tx * 4 + 0];
            float b1 = kst[d * 65 + tx * 4 + 1];
            float b2 = kst[d * 65 + tx * 4 + 2];
            float b3 = kst[d * 65 + tx * 4 + 3];
            sacc[0][0] += a0 * b0; sacc[0][1] += a0 * b1; sacc[0][2] += a0 * b2; sacc[0][3] += a0 * b3;
            sacc[1][0] += a1 * b0; sacc[1][1] += a1 * b1; sacc[1][2] += a1 * b2; sacc[1][3] += a1 * b3;
            sacc[2][0] += a2 * b0; sacc[2][1] += a2 * b1; sacc[2][2] += a2 * b2; sacc[2][3] += a2 * b3;
            sacc[3][0] += a3 * b0; sacc[3][1] += a3 * b1; sacc[3][2] += a3 * b2; sacc[3][3] += a3 * b3;
        }
        // causal mask + store scores
        #pragma unroll
        for (int i = 0; i < 4; i++) {
            int gm = m0 + ty * 4 + i;
            #pragma unroll
            for (int j = 0; j < 4; j++) {
                int gn = kn + tx * 4 + j;
                ss[(ty * 4 + i) * 68 + tx * 4 + j] = (gn <= gm) ? sacc[i][j] : -1e30f;
            }
        }
        __syncthreads();

        // row max (each of the 4 threads per row scans the full row)
        float tmax = -1e30f;
        #pragma unroll 8
        for (int n = 0; n < 64; n++) tmax = fmaxf(tmax, ss[r * 68 + n]);
        float mnew  = fmaxf(mrow, tmax);
        float alpha = __expf(mrow - mnew);
        __syncthreads();  // everyone done reading raw scores

        // exp (split across the 4 threads of the row), write p back to ss
        #pragma unroll
        for (int n = cg * 16; n < cg * 16 + 16; n++)
            ss[r * 68 + n] = __expf(ss[r * 68 + n] - mnew);
        mrow = mnew;
        lrow *= alpha;
        #pragma unroll
        for (int j = 0; j < 32; j++) acc[j] *= alpha;
        __syncthreads();

        // AV: acc[c] += p[n] * v[n][c], thread owns cols cg + 4*j
        for (int n = 0; n < 64; n++) {
            float p = ss[r * 68 + n];
            lrow += p;
            #pragma unroll
            for (int j = 0; j < 32; j++)
                acc[j] += p * vs[n * 128 + cg + 4 * j];
        }
    }

    // epilogue: o = acc / l * 2048^-0.5, layout [B,T,H*D]
    const float inv = 0.022097086912079608f / lrow;
    float* og = o + ((size_t)(b * TT + m0 + r)) * NE + h * HD + cg;
    #pragma unroll
    for (int j = 0; j < 32; j++)
        og[4 * j] = acc[j] * inv;
}

// ---------------------------------------------------------------------------
// launch
// ---------------------------------------------------------------------------
extern "C" void kernel_launch(void* const* d_in, const int* in_sizes, int n_in,
                              void* d_out, int out_size)
{
    const float* x  = (const float*)d_in[0];
    const float* Wq = (const float*)d_in[1];
    const float* bq = (const float*)d_in[2];
    const float* Wk = (const float*)d_in[3];
    const float* bk = (const float*)d_in[4];
    const float* Wv = (const float*)d_in[5];
    const float* bv = (const float*)d_in[6];
    const float* Wo = (const float*)d_in[7];
    const float* bo = (const float*)d_in[8];
    float* out = (float*)d_out;

    float *qb, *kb, *vb, *ob, *ct, *st;
    __nv_bfloat16 *qr, *kr;
    cudaGetSymbolAddress((void**)&qb, g_q);
    cudaGetSymbolAddress((void**)&kb, g_k);
    cudaGetSymbolAddress((void**)&vb, g_v);
    cudaGetSymbolAddress((void**)&ob, g_o);
    cudaGetSymbolAddress((void**)&ct, g_cos);
    cudaGetSymbolAddress((void**)&st, g_sin);
    cudaGetSymbolAddress((void**)&qr, g_qr);
    cudaGetSymbolAddress((void**)&kr, g_kr);

    // Q projection: [4096,2048] @ [2048,2048]
    {
        dim3 grid(NE / 128, MROWS / 128, 1);
        gemm_bias_kernel<<<grid, 256>>>(x, Wq, bq, qb, MROWS, NE, NE);
    }
    // K and V projections fused over blockIdx.z: [4096,2048] @ [2048,512]
    {
        dim3 grid(KVDIM / 128, MROWS / 128, 2);
        gemm_kv_kernel<<<grid, 256>>>(x, Wk, bk, kb, Wv, bv, vb, MROWS, KVDIM, NE);
    }
    // RoPE tables + apply
    rope_table_kernel<<<(TT * 64 + 255) / 256, 256>>>(ct, st);
    rope_q_kernel<<<(BB * TT * NH * 64) / 256, 256>>>(qb, ct, st, qr);
    rope_k_kernel<<<(BB * TT * NKV * 64) / 256, 256>>>(kb, ct, st, kr);

    // attention
    {
        size_t smem = (size_t)ATTN_SMEM_FLOATS * sizeof(float);
        cudaFuncSetAttribute(attn_kernel, cudaFuncAttributeMaxDynamicSharedMemorySize, (int)smem);
        dim3 grid(TT / 64, NH, BB);
        attn_kernel<<<grid, 256, smem>>>(qr, kr, vb, ob);
    }

    // output projection: [4096,2048] @ [2048,2048] -> d_out
    {
        dim3 grid(NE / 128, MROWS / 128, 1);
        gemm_bias_kernel<<<grid, 256>>>(ob, Wo, bo, out, MROWS, NE, NE);
    }
}

// round 3
// speedup vs baseline: 1.0004x; 1.0004x over previous
#include <cuda_runtime.h>
#include <cuda_bf16.h>
#include <cstdint>
#include <cmath>

// ---------------------------------------------------------------------------
// Problem constants (fixed shapes)
// ---------------------------------------------------------------------------
#define BB 2
#define TT 2048
#define NE 2048          // N_EMBED
#define NH 16            // N_HEAD
#define NKV 4            // N_KV_HEAD
#define HD 128           // HEAD_DIM
#define MROWS (BB*TT)    // 4096
#define KVDIM (NKV*HD)   // 512

// ---------------------------------------------------------------------------
// Scratch (static device globals; no allocations allowed)
// ---------------------------------------------------------------------------
__device__ float g_q[(size_t)MROWS * NE];       // x@Wq+bq
__device__ float g_k[(size_t)MROWS * KVDIM];    // x@Wk+bk
__device__ float g_v[(size_t)MROWS * KVDIM];    // x@Wv+bv
__device__ float g_o[(size_t)MROWS * NE];       // attention output [B,T,H*D]
__device__ __nv_bfloat16 g_qr[(size_t)BB * NH * TT * HD];   // rope(q) bf16 [B,H,T,D]
__device__ __nv_bfloat16 g_kr[(size_t)BB * NKV * TT * HD];  // rope(k) bf16 [B,KV,T,D]
__device__ float g_cos[TT * (HD/2)];
__device__ float g_sin[TT * (HD/2)];

// ---------------------------------------------------------------------------
// SGEMM: C[M,N] = A[M,K] @ B[K,N] + bias[N]   (all row-major, fp32)
// 128x128 block tile, BK=16, 256 threads, 8x8 per-thread micro-tile.
// M % 128 == 0, N % 128 == 0, K % 16 == 0 (true for all our shapes).
// ---------------------------------------------------------------------------
__device__ __forceinline__ void gemm_body(const float* __restrict__ A,
                                          const float* __restrict__ B,
                                          const float* __restrict__ bias,
                                          float* __restrict__ C,
                                          int M, int N, int K)
{
    __shared__ float As[16 * 128];   // transposed: As[k][m]
    __shared__ float Bs[16 * 128];   // Bs[k][n]

    const int tid = threadIdx.x;     // 0..255
    const int tx  = tid & 15;        // N micro index
    const int ty  = tid >> 4;        // M micro index
    const int m0  = blockIdx.y * 128;
    const int n0  = blockIdx.x * 128;

    float acc[8][8];
    #pragma unroll
    for (int i = 0; i < 8; i++)
        #pragma unroll
        for (int j = 0; j < 8; j++) acc[i][j] = 0.f;

    for (int k0 = 0; k0 < K; k0 += 16) {
        // load A tile (128 rows x 16 cols), store transposed
        #pragma unroll
        for (int s = 0; s < 2; s++) {
            int f   = tid * 2 + s;           // 0..511
            int row = f >> 2;                // 0..127
            int kq  = (f & 3) << 2;          // 0,4,8,12
            float4 av = *(const float4*)&A[(size_t)(m0 + row) * K + k0 + kq];
            As[(kq + 0) * 128 + row] = av.x;
            As[(kq + 1) * 128 + row] = av.y;
            As[(kq + 2) * 128 + row] = av.z;
            As[(kq + 3) * 128 + row] = av.w;
        }
        // load B tile (16 rows x 128 cols)
        #pragma unroll
        for (int s = 0; s < 2; s++) {
            int f   = tid * 2 + s;
            int row = f >> 5;                // 0..15
            int c4  = (f & 31) << 2;         // 0..124
            *(float4*)&Bs[row * 128 + c4] =
                *(const float4*)&B[(size_t)(k0 + row) * N + n0 + c4];
        }
        __syncthreads();

        #pragma unroll
        for (int k = 0; k < 16; k++) {
            float a[8], bv[8];
            *(float4*)&a[0]  = *(float4*)&As[k * 128 + ty * 4];
            *(float4*)&a[4]  = *(float4*)&As[k * 128 + 64 + ty * 4];
            *(float4*)&bv[0] = *(float4*)&Bs[k * 128 + tx * 4];
            *(float4*)&bv[4] = *(float4*)&Bs[k * 128 + 64 + tx * 4];
            #pragma unroll
            for (int i = 0; i < 8; i++)
                #pragma unroll
                for (int j = 0; j < 8; j++)
                    acc[i][j] += a[i] * bv[j];
        }
        __syncthreads();
    }

    // epilogue: add bias, store
    #pragma unroll
    for (int ih = 0; ih < 2; ih++) {
        #pragma unroll
        for (int i = 0; i < 4; i++) {
            int gm = m0 + ih * 64 + ty * 4 + i;
            #pragma unroll
            for (int jh = 0; jh < 2; jh++) {
                int gn = n0 + jh * 64 + tx * 4;
                float4 bv = *(const float4*)&bias[gn];
                float4 o;
                o.x = acc[ih * 4 + i][jh * 4 + 0] + bv.x;
                o.y = acc[ih * 4 + i][jh * 4 + 1] + bv.y;
                o.z = acc[ih * 4 + i][jh * 4 + 2] + bv.z;
                o.w = acc[ih * 4 + i][jh * 4 + 3] + bv.w;
                *(float4*)&C[(size_t)gm * N + gn] = o;
            }
        }
    }
}

__global__ void __launch_bounds__(256)
gemm_bias_kernel(const float* __restrict__ A, const float* __restrict__ B,
                 const float* __restrict__ bias, float* __restrict__ C,
                 int M, int N, int K)
{
    gemm_body(A, B, bias, C, M, N, K);
}

__global__ void __launch_bounds__(256)
gemm_kv_kernel(const float* __restrict__ A,
               const float* __restrict__ B0, const float* __restrict__ bias0, float* __restrict__ C0,
               const float* __restrict__ B1, const float* __restrict__ bias1, float* __restrict__ C1,
               int M, int N, int K)
{
    const float* B    = blockIdx.z ? B1    : B0;
    const float* bias = blockIdx.z ? bias1 : bias0;
    float*       C    = blockIdx.z ? C1    : C0;
    gemm_body(A, B, bias, C, M, N, K);
}

// ---------------------------------------------------------------------------
// RoPE table: angle = fp32(t) * fp32(double-precision freq), matching the
// reference's fp32 pipeline as closely as possible.
// ---------------------------------------------------------------------------
__global__ void __launch_bounds__(256)
rope_table_kernel(float* __restrict__ ct, float* __restrict__ st)
{
    int idx = blockIdx.x * 256 + threadIdx.x;
    if (idx >= TT * (HD/2)) return;
    int t = idx >> 6;
    int i = idx & 63;
    double fr = exp(-((double)(2 * i) / (double)NE) * log(10000.0));
    float ff = (float)fr;
    float ang = __fmul_rn((float)t, ff);
    float s, c;
    sincosf(ang, &s, &c);
    ct[idx] = c;
    st[idx] = s;
}

// rope + bf16 round for Q: [B,T,H,D] fp32 -> [B,H,T,D] bf16
__global__ void __launch_bounds__(256)
rope_q_kernel(const float* __restrict__ q, const float* __restrict__ ct,
              const float* __restrict__ st, __nv_bfloat16* __restrict__ qr)
{
    int idx = blockIdx.x * 256 + threadIdx.x;   // total BB*TT*NH*64
    int i = idx & 63;
    int h = (idx >> 6) & 15;
    int t = (idx >> 10) & 2047;
    int b = idx >> 21;
    size_t src = ((size_t)(b * TT + t)) * NE + h * HD + 2 * i;
    float xr = q[src], xi = q[src + 1];
    float c = ct[t * 64 + i], s = st[t * 64 + i];
    float orr = xr * c - xi * s;
    float oii = xr * s + xi * c;
    size_t dst = ((size_t)((b * NH + h) * TT + t)) * HD + 2 * i;
    qr[dst]     = __float2bfloat16(orr);
    qr[dst + 1] = __float2bfloat16(oii);
}

// rope + bf16 round for K: [B,T,KV,D] fp32 -> [B,KV,T,D] bf16
__global__ void __launch_bounds__(256)
rope_k_kernel(const float* __restrict__ k, const float* __restrict__ ct,
              const float* __restrict__ st, __nv_bfloat16* __restrict__ kr)
{
    int idx = blockIdx.x * 256 + threadIdx.x;   // total BB*TT*NKV*64
    int i = idx & 63;
    int h = (idx >> 6) & 3;
    int t = (idx >> 8) & 2047;
    int b = idx >> 19;
    size_t src = ((size_t)(b * TT + t)) * KVDIM + h * HD + 2 * i;
    float xr = k[src], xi = k[src + 1];
    float c = ct[t * 64 + i], s = st[t * 64 + i];
    float orr = xr * c - xi * s;
    float oii = xr * s + xi * c;
    size_t dst = ((size_t)((b * NKV + h) * TT + t)) * HD + 2 * i;
    kr[dst]     = __float2bfloat16(orr);
    kr[dst + 1] = __float2bfloat16(oii);
}

// ---------------------------------------------------------------------------
// Flash attention (causal, GQA). fp32 SIMT. BM=BN=64, 256 threads.
// attn = softmax(q@k^T) * 2048^-0.5;  o = attn @ v.
// smem: qs[64][128] | kst[128][65] (k transposed) | vs[64][128] | ss[64][68]
// ---------------------------------------------------------------------------
#define ATTN_SMEM_FLOATS (64*128 + 128*65 + 64*128 + 64*68)

__global__ void __launch_bounds__(256)
attn_kernel(const __nv_bfloat16* __restrict__ qr, const __nv_bfloat16* __restrict__ kr,
            const float* __restrict__ v, float* __restrict__ o)
{
    extern __shared__ float sm[];
    float* qs  = sm;                       // 8192
    float* kst = sm + 64 * 128;            // 8320 (stride 65)
    float* vs  = kst + 128 * 65;           // 8192
    float* ss  = vs + 64 * 128;            // 64*68 (stride 68)

    const int tid = threadIdx.x;
    const int mt = blockIdx.x, h = blockIdx.y, b = blockIdx.z;
    const int m0 = mt * 64;
    const int kv = h >> 2;                 // REPEAT = 4

    const __nv_bfloat16* qg = qr + ((size_t)(b * NH + h) * TT + m0) * HD;
    const __nv_bfloat16* kg = kr + ((size_t)(b * NKV + kv) * TT) * HD;
    const float*         vg = v  + ((size_t)b * TT) * KVDIM + kv * HD;

    // load q tile -> qs (fp32)
    for (int idx = tid; idx < 64 * 16; idx += 256) {
        int r  = idx >> 4;
        int d8 = (idx & 15) << 3;
        uint4 u = *(const uint4*)(qg + (size_t)r * HD + d8);
        const __nv_bfloat16* pb = (const __nv_bfloat16*)&u;
        #pragma unroll
        for (int j = 0; j < 8; j++)
            qs[r * 128 + d8 + j] = __bfloat162float(pb[j]);
    }

    float acc[32];
    #pragma unroll
    for (int j = 0; j < 32; j++) acc[j] = 0.f;
    float mrow = -1e30f, lrow = 0.f;

    const int r  = tid >> 2;   // row 0..63 (softmax/AV stage)
    const int cg = tid & 3;    // column group
    const int tx = tid & 15;   // score micro-tile N
    const int ty = tid >> 4;   // score micro-tile M

    const int ntile = mt + 1;  // causal: keys up to m0+63
    for (int jt = 0; jt < ntile; jt++) {
        const int kn = jt * 64;
        __syncthreads();  // previous tile fully consumed (and q loaded, 1st iter)

        // load k tile transposed: kst[d][n]
        for (int idx = tid; idx < 64 * 16; idx += 256) {
            int n  = idx >> 4;
            int d8 = (idx & 15) << 3;
            uint4 u = *(const uint4*)(kg + (size_t)(kn + n) * HD + d8);
            const __nv_bfloat16* pb = (const __nv_bfloat16*)&u;
            #pragma unroll
            for (int j = 0; j < 8; j++)
                kst[(d8 + j) * 65 + n] = __bfloat162float(pb[j]);
        }
        // load v tile: vs[n][c]
        for (int idx = tid; idx < 64 * 32; idx += 256) {
            int n  = idx >> 5;
            int c4 = (idx & 31) << 2;
            *(float4*)&vs[n * 128 + c4] =
                *(const float4*)(vg + (size_t)(kn + n) * KVDIM + c4);
        }
        __syncthreads();

        // scores: s = q @ k^T  (64x64x128), 4x4 micro-tile per thread
        float sacc[4][4];
        #pragma unroll
        for (int i = 0; i < 4; i++)
            #pragma unroll
            for (int j = 0; j < 4; j++) sacc[i][j] = 0.f;

        #pragma unroll 4
        for (int d = 0; d < 128; d++) {
            float a0 = qs[(ty * 4 + 0) * 128 + d];
            float a1 = qs[(ty * 4 + 1) * 128 + d];
            float a2 = qs[(ty * 4 + 2) * 128 + d];
            float a3 = qs[(ty * 4 + 3) * 128 + d];
            float b0 = kst[d * 65 + tx * 4 + 0];
            float b1 = kst[d * 65 + tx * 4 + 1];
            float b2 = kst[d * 65 + tx * 4 + 2];
            float b3 = kst[d * 65 + tx * 4 + 3];
            sacc[0][0] += a0 * b0; sacc[0][1] += a0 * b1; sacc[0][2] += a0 * b2; sacc[0][3] += a0 * b3;
            sacc[1][0] += a1 * b0; sacc[1][1] += a1 * b1; sacc[1][2] += a1 * b2; sacc[1][3] += a1 * b3;
            sacc[2][0] += a2 * b0; sacc[2][1] += a2 * b1; sacc[2][2] += a2 * b2; sacc[2][3] += a2 * b3;
            sacc[3][0] += a3 * b0; sacc[3][1] += a3 * b1; sacc[3][2] += a3 * b2; sacc[3][3] += a3 * b3;
        }
        // causal mask + store scores
        #pragma unroll
        for (int i = 0; i < 4; i++) {
            int gm = m0 + ty * 4 + i;
            #pragma unroll
            for (int j = 0; j < 4; j++) {
                int gn = kn + tx * 4 + j;
                ss[(ty * 4 + i) * 68 + tx * 4 + j] = (gn <= gm) ? sacc[i][j] : -1e30f;
            }
        }
        __syncthreads();

        // row max (each of the 4 threads per row scans the full row)
        float tmax = -1e30f;
        #pragma unroll 8
        for (int n = 0; n < 64; n++) tmax = fmaxf(tmax, ss[r * 68 + n]);
        float mnew  = fmaxf(mrow, tmax);
        float alpha = __expf(mrow - mnew);
        __syncthreads();  // everyone done reading raw scores

        // exp (split across the 4 threads of the row), write p back to ss
        #pragma unroll
        for (int n = cg * 16; n < cg * 16 + 16; n++)
            ss[r * 68 + n] = __expf(ss[r * 68 + n] - mnew);
        mrow = mnew;
        lrow *= alpha;
        #pragma unroll
        for (int j = 0; j < 32; j++) acc[j] *= alpha;
        __syncthreads();

        // AV: acc[c] += p[n] * v[n][c], thread owns cols cg + 4*j
        for (int n = 0; n < 64; n++) {
            float p = ss[r * 68 + n];
            lrow += p;
            #pragma unroll
            for (int j = 0; j < 32; j++)
                acc[j] += p * vs[n * 128 + cg + 4 * j];
        }
    }

    // epilogue: o = acc / l * 2048^-0.5, layout [B,T,H*D]
    const float inv = 0.022097086912079608f / lrow;
    float* og = o + ((size_t)(b * TT + m0 + r)) * NE + h * HD + cg;
    #pragma unroll
    for (int j = 0; j < 32; j++)
        og[4 * j] = acc[j] * inv;
}

// ---------------------------------------------------------------------------
// launch
// ---------------------------------------------------------------------------
extern "C" void kernel_launch(void* const* d_in, const int* in_sizes, int n_in,
                              void* d_out, int out_size)
{
    const float* x  = (const float*)d_in[0];
    const float* Wq = (const float*)d_in[1];
    const float* bq = (const float*)d_in[2];
    const float* Wk = (const float*)d_in[3];
    const float* bk = (const float*)d_in[4];
    const float* Wv = (const float*)d_in[5];
    const float* bv = (const float*)d_in[6];
    const float* Wo = (const float*)d_in[7];
    const float* bo = (const float*)d_in[8];
    float* out = (float*)d_out;

    float *qb, *kb, *vb, *ob, *ct, *st;
    __nv_bfloat16 *qr, *kr;
    cudaGetSymbolAddress((void**)&qb, g_q);
    cudaGetSymbolAddress((void**)&kb, g_k);
    cudaGetSymbolAddress((void**)&vb, g_v);
    cudaGetSymbolAddress((void**)&ob, g_o);
    cudaGetSymbolAddress((void**)&ct, g_cos);
    cudaGetSymbolAddress((void**)&st, g_sin);
    cudaGetSymbolAddress((void**)&qr, g_qr);
    cudaGetSymbolAddress((void**)&kr, g_kr);

    // Q projection: [4096,2048] @ [2048,2048]
    {
        dim3 grid(NE / 128, MROWS / 128, 1);
        gemm_bias_kernel<<<grid, 256>>>(x, Wq, bq, qb, MROWS, NE, NE);
    }
    // K and V projections fused over blockIdx.z: [4096,2048] @ [2048,512]
    {
        dim3 grid(KVDIM / 128, MROWS / 128, 2);
        gemm_kv_kernel<<<grid, 256>>>(x, Wk, bk, kb, Wv, bv, vb, MROWS, KVDIM, NE);
    }
    // RoPE tables + apply
    rope_table_kernel<<<(TT * 64 + 255) / 256, 256>>>(ct, st);
    rope_q_kernel<<<(BB * TT * NH * 64) / 256, 256>>>(qb, ct, st, qr);
    rope_k_kernel<<<(BB * TT * NKV * 64) / 256, 256>>>(kb, ct, st, kr);

    // attention
    {
        size_t smem = (size_t)ATTN_SMEM_FLOATS * sizeof(float);
        cudaFuncSetAttribute(attn_kernel, cudaFuncAttributeMaxDynamicSharedMemorySize, (int)smem);
        dim3 grid(TT / 64, NH, BB);
        attn_kernel<<<grid, 256, smem>>>(qr, kr, vb, ob);
    }

    // output projection: [4096,2048] @ [2048,2048] -> d_out
    {
        dim3 grid(NE / 128, MROWS / 128, 1);
        gemm_bias_kernel<<<grid, 256>>>(ob, Wo, bo, out, MROWS, NE, NE);
    }
}

// round 5
// speedup vs baseline: 1.1045x; 1.1042x over previous
#include <cuda_runtime.h>
#include <cuda_bf16.h>
#include <cstdint>
#include <cmath>

// ---------------------------------------------------------------------------
// Problem constants (fixed shapes)
// ---------------------------------------------------------------------------
#define BB 2
#define TT 2048
#define NE 2048          // N_EMBED
#define NH 16            // N_HEAD
#define NKV 4            // N_KV_HEAD
#define HD 128           // HEAD_DIM
#define MROWS (BB*TT)    // 4096
#define KVDIM (NKV*HD)   // 512

// ---------------------------------------------------------------------------
// Scratch (static device globals; no allocations allowed)
// ---------------------------------------------------------------------------
__device__ float g_q[(size_t)MROWS * NE];       // x@Wq+bq
__device__ float g_k[(size_t)MROWS * KVDIM];    // x@Wk+bk
__device__ float g_v[(size_t)MROWS * KVDIM];    // x@Wv+bv
__device__ float g_o[(size_t)MROWS * NE];       // attention output [B,T,H*D]
__device__ __nv_bfloat16 g_qr[(size_t)BB * NH * TT * HD];   // rope(q) bf16 [B,H,T,D]
__device__ __nv_bfloat16 g_kr[(size_t)BB * NKV * TT * HD];  // rope(k) bf16 [B,KV,T,D]
__device__ float g_cos[TT * (HD/2)];
__device__ float g_sin[TT * (HD/2)];

// split-bf16 operands for tensor-core GEMMs
__device__ __nv_bfloat16 g_xh[(size_t)MROWS * NE];
__device__ __nv_bfloat16 g_xl[(size_t)MROWS * NE];
__device__ __nv_bfloat16 g_oh[(size_t)MROWS * NE];
__device__ __nv_bfloat16 g_ol[(size_t)MROWS * NE];
// transposed weights [N][K], hi/lo
__device__ __nv_bfloat16 g_wqh[(size_t)NE * NE];
__device__ __nv_bfloat16 g_wql[(size_t)NE * NE];
__device__ __nv_bfloat16 g_wkh[(size_t)KVDIM * NE];
__device__ __nv_bfloat16 g_wkl[(size_t)KVDIM * NE];
__device__ __nv_bfloat16 g_wvh[(size_t)KVDIM * NE];
__device__ __nv_bfloat16 g_wvl[(size_t)KVDIM * NE];
__device__ __nv_bfloat16 g_woh[(size_t)NE * NE];
__device__ __nv_bfloat16 g_wol[(size_t)NE * NE];

// ---------------------------------------------------------------------------
// Helpers (baseline PTX only — no sm_103a-suffixed features)
// ---------------------------------------------------------------------------
__device__ __forceinline__ uint32_t smem_u32(const void* p) {
    uint32_t a;
    asm("{ .reg .u64 t; cvta.to.shared.u64 t, %1; cvt.u32.u64 %0, t; }" : "=r"(a) : "l"(p));
    return a;
}
__device__ __forceinline__ uint32_t sw128(uint32_t off) {
    return off ^ ((off >> 3) & 0x70);
}
__device__ __forceinline__ void cp16(uint32_t dst, const void* src) {
    asm volatile("cp.async.cg.shared.global [%0], [%1], 16;" :: "r"(dst), "l"(src) : "memory");
}
__device__ __forceinline__ void ldsm4(uint32_t* r, uint32_t addr) {
    asm volatile("ldmatrix.sync.aligned.m8n8.x4.shared.b16 {%0,%1,%2,%3}, [%4];"
                 : "=r"(r[0]), "=r"(r[1]), "=r"(r[2]), "=r"(r[3]) : "r"(addr));
}
__device__ __forceinline__ void mma16816(float* c, const uint32_t* a, const uint32_t* b) {
    asm volatile(
        "mma.sync.aligned.m16n8k16.row.col.f32.bf16.bf16.f32 "
        "{%0,%1,%2,%3}, {%4,%5,%6,%7}, {%8,%9}, {%0,%1,%2,%3};"
        : "+f"(c[0]), "+f"(c[1]), "+f"(c[2]), "+f"(c[3])
        : "r"(a[0]), "r"(a[1]), "r"(a[2]), "r"(a[3]), "r"(b[0]), "r"(b[1]));
}

// ---------------------------------------------------------------------------
// Prep kernels: split fp32 -> hi/lo bf16; transpose+split weights
// ---------------------------------------------------------------------------
__global__ void __launch_bounds__(256)
split_kernel(const float* __restrict__ x, __nv_bfloat16* __restrict__ xh,
             __nv_bfloat16* __restrict__ xl, int n8)
{
    int i = blockIdx.x * 256 + threadIdx.x;
    if (i >= n8) return;
    size_t base = (size_t)i * 8;
    float4 v0 = *(const float4*)(x + base);
    float4 v1 = *(const float4*)(x + base + 4);
    float vv[8] = {v0.x, v0.y, v0.z, v0.w, v1.x, v1.y, v1.z, v1.w};
    union { __nv_bfloat16 b[8]; uint4 u; } ph, pl;
    #pragma unroll
    for (int j = 0; j < 8; j++) {
        __nv_bfloat16 h = __float2bfloat16(vv[j]);
        ph.b[j] = h;
        pl.b[j] = __float2bfloat16(vv[j] - __bfloat162float(h));
    }
    *(uint4*)(xh + base) = ph.u;
    *(uint4*)(xl + base) = pl.u;
}

// W[K][N] row-major -> Th/Tl[N][K] bf16
__global__ void __launch_bounds__(256)
tsplit_kernel(const float* __restrict__ W, __nv_bfloat16* __restrict__ Th,
              __nv_bfloat16* __restrict__ Tl, int K, int N)
{
    __shared__ float t[32][33];
    int n0 = blockIdx.x * 32, k0 = blockIdx.y * 32;
    int tx = threadIdx.x & 31, ty = threadIdx.x >> 5;   // 32x8
    #pragma unroll
    for (int i = 0; i < 4; i++)
        t[ty + i * 8][tx] = W[(size_t)(k0 + ty + i * 8) * N + n0 + tx];
    __syncthreads();
    #pragma unroll
    for (int i = 0; i < 4; i++) {
        int n = n0 + ty + i * 8, k = k0 + tx;
        float v = t[tx][ty + i * 8];
        __nv_bfloat16 h = __float2bfloat16(v);
        Th[(size_t)n * K + k] = h;
        Tl[(size_t)n * K + k] = __float2bfloat16(v - __bfloat162float(h));
    }
}

// ---------------------------------------------------------------------------
// mma.sync split-bf16 GEMM: C[M,N] = Ah@Bh^T + Ah@Bl^T + Al@Bh^T + bias
// A*[M,K] bf16 K-major; B*[N,K] bf16 K-major (pre-transposed weights).
// BM=128, BN=128, BK=64, 256 threads (4m x 2n warps), 2-stage cp.async.
// Stage layout: Ah@0 | Al@16K | Bh@32K | Bl@48K  (each 128 rows x 128B, SW128)
// ---------------------------------------------------------------------------
#define STG_BYTES 65536
#define GEMM_SMEM (2*STG_BYTES + 1024)

__global__ void __launch_bounds__(256, 1)
gemm_mma_kernel(const __nv_bfloat16* __restrict__ Ah, const __nv_bfloat16* __restrict__ Al,
                const __nv_bfloat16* __restrict__ BTh, const __nv_bfloat16* __restrict__ BTl,
                const float* __restrict__ bias, float* __restrict__ C,
                int M, int N, int K)
{
    extern __shared__ char dsm[];
    char* smbase = (char*)(((uintptr_t)dsm + 1023) & ~(uintptr_t)1023);
    const uint32_t sb = smem_u32(smbase);

    const int tid  = threadIdx.x;
    const int lane = tid & 31;
    const int wid  = tid >> 5;
    const int wm   = wid >> 1;          // 0..3
    const int wn   = wid & 1;           // 0..1
    const int m0   = blockIdx.y * 128;
    const int n0   = blockIdx.x * 128;

    const int nstage = K / 64;

    float c[2][8][4];
    #pragma unroll
    for (int im = 0; im < 2; im++)
        #pragma unroll
        for (int in = 0; in < 8; in++)
            #pragma unroll
            for (int j = 0; j < 4; j++) c[im][in][j] = 0.f;

    // ---- stage loader ----
    auto load_stage = [&](int s) {
        const int k0 = s * 64;
        const uint32_t stg = sb + (s & 1) * STG_BYTES;
        #pragma unroll
        for (int i = 0; i < 16; i++) {
            int idx = tid + (i << 8);
            int tl  = idx >> 10;            // 0:Ah 1:Al 2:Bh 3:Bl
            int row = (idx >> 3) & 127;
            int q   = idx & 7;
            const __nv_bfloat16* src;
            if (tl == 0)      src = Ah  + (size_t)(m0 + row) * K + k0 + q * 8;
            else if (tl == 1) src = Al  + (size_t)(m0 + row) * K + k0 + q * 8;
            else if (tl == 2) src = BTh + (size_t)(n0 + row) * K + k0 + q * 8;
            else              src = BTl + (size_t)(n0 + row) * K + k0 + q * 8;
            cp16(stg + tl * 16384 + sw128((uint32_t)(row * 128 + q * 16)), src);
        }
    };

    load_stage(0);
    asm volatile("cp.async.commit_group;" ::: "memory");

    // precomputed ldmatrix lane offsets
    const int aRow  = (lane & 15);                 // within 16-row block
    const int aKoff = (lane >> 4) << 4;            // 0 or 16 bytes
    const int bRow  = (lane & 7) + ((lane >> 4) << 3);   // within 16-row block
    const int bKoff = ((lane >> 3) & 1) << 4;      // 0 or 16 bytes

    for (int s = 0; s < nstage; s++) {
        if (s + 1 < nstage) load_stage(s + 1);
        asm volatile("cp.async.commit_group;" ::: "memory");
        if (s + 1 < nstage) asm volatile("cp.async.wait_group 1;" ::: "memory");
        else                asm volatile("cp.async.wait_group 0;" ::: "memory");
        __syncthreads();

        const uint32_t ab = sb + (s & 1) * STG_BYTES;

        #pragma unroll
        for (int kk = 0; kk < 4; kk++) {
            const int kb = kk * 32;
            uint32_t a_h[2][4], a_l[2][4];
            #pragma unroll
            for (int im = 0; im < 2; im++) {
                uint32_t off = sw128((uint32_t)((wm * 32 + im * 16 + aRow) * 128 + kb + aKoff));
                ldsm4(a_h[im], ab + off);
                ldsm4(a_l[im], ab + 16384 + off);
            }
            uint32_t b_h[16], b_l[16];
            #pragma unroll
            for (int ib = 0; ib < 4; ib++) {
                uint32_t off = sw128((uint32_t)((wn * 64 + ib * 16 + bRow) * 128 + kb + bKoff));
                ldsm4(&b_h[ib * 4], ab + 32768 + off);
                ldsm4(&b_l[ib * 4], ab + 49152 + off);
            }
            #pragma unroll
            for (int im = 0; im < 2; im++) {
                #pragma unroll
                for (int in = 0; in < 8; in++) {
                    const uint32_t* bh = &b_h[(in >> 1) * 4 + (in & 1) * 2];
                    const uint32_t* bl = &b_l[(in >> 1) * 4 + (in & 1) * 2];
                    mma16816(c[im][in], a_h[im], bh);
                    mma16816(c[im][in], a_l[im], bh);
                    mma16816(c[im][in], a_h[im], bl);
                }
            }
        }
        __syncthreads();
    }

    // epilogue: add bias, store fp32
    #pragma unroll
    for (int im = 0; im < 2; im++) {
        const int r0 = m0 + wm * 32 + im * 16 + (lane >> 2);
        #pragma unroll
        for (int in = 0; in < 8; in++) {
            const int cc = n0 + wn * 64 + in * 8 + ((lane & 3) << 1);
            float2 bb = *(const float2*)&bias[cc];
            float2 o0, o1;
            o0.x = c[im][in][0] + bb.x;  o0.y = c[im][in][1] + bb.y;
            o1.x = c[im][in][2] + bb.x;  o1.y = c[im][in][3] + bb.y;
            *(float2*)&C[(size_t)r0 * N + cc]       = o0;
            *(float2*)&C[(size_t)(r0 + 8) * N + cc] = o1;
        }
    }
}

// ---------------------------------------------------------------------------
// RoPE table: angle = fp32(t) * fp32(double-precision freq)
// ---------------------------------------------------------------------------
__global__ void __launch_bounds__(256)
rope_table_kernel(float* __restrict__ ct, float* __restrict__ st)
{
    int idx = blockIdx.x * 256 + threadIdx.x;
    if (idx >= TT * (HD/2)) return;
    int t = idx >> 6;
    int i = idx & 63;
    double fr = exp(-((double)(2 * i) / (double)NE) * log(10000.0));
    float ff = (float)fr;
    float ang = __fmul_rn((float)t, ff);
    float s, c;
    sincosf(ang, &s, &c);
    ct[idx] = c;
    st[idx] = s;
}

__global__ void __launch_bounds__(256)
rope_q_kernel(const float* __restrict__ q, const float* __restrict__ ct,
              const float* __restrict__ st, __nv_bfloat16* __restrict__ qr)
{
    int idx = blockIdx.x * 256 + threadIdx.x;
    int i = idx & 63;
    int h = (idx >> 6) & 15;
    int t = (idx >> 10) & 2047;
    int b = idx >> 21;
    size_t src = ((size_t)(b * TT + t)) * NE + h * HD + 2 * i;
    float xr = q[src], xi = q[src + 1];
    float c = ct[t * 64 + i], s = st[t * 64 + i];
    float orr = xr * c - xi * s;
    float oii = xr * s + xi * c;
    size_t dst = ((size_t)((b * NH + h) * TT + t)) * HD + 2 * i;
    qr[dst]     = __float2bfloat16(orr);
    qr[dst + 1] = __float2bfloat16(oii);
}

__global__ void __launch_bounds__(256)
rope_k_kernel(const float* __restrict__ k, const float* __restrict__ ct,
              const float* __restrict__ st, __nv_bfloat16* __restrict__ kr)
{
    int idx = blockIdx.x * 256 + threadIdx.x;
    int i = idx & 63;
    int h = (idx >> 6) & 3;
    int t = (idx >> 8) & 2047;
    int b = idx >> 19;
    size_t src = ((size_t)(b * TT + t)) * KVDIM + h * HD + 2 * i;
    float xr = k[src], xi = k[src + 1];
    float c = ct[t * 64 + i], s = st[t * 64 + i];
    float orr = xr * c - xi * s;
    float oii = xr * s + xi * c;
    size_t dst = ((size_t)((b * NKV + h) * TT + t)) * HD + 2 * i;
    kr[dst]     = __float2bfloat16(orr);
    kr[dst + 1] = __float2bfloat16(oii);
}

// ---------------------------------------------------------------------------
// Flash attention (causal, GQA). fp32 SIMT. BM=BN=64, 256 threads.
// ---------------------------------------------------------------------------
#define ATTN_SMEM_FLOATS (64*128 + 128*65 + 64*128 + 64*68)

__global__ void __launch_bounds__(256)
attn_kernel(const __nv_bfloat16* __restrict__ qr, const __nv_bfloat16* __restrict__ kr,
            const float* __restrict__ v, float* __restrict__ o)
{
    extern __shared__ float sm[];
    float* qs  = sm;
    float* kst = sm + 64 * 128;
    float* vs  = kst + 128 * 65;
    float* ss  = vs + 64 * 128;

    const int tid = threadIdx.x;
    const int mt = blockIdx.x, h = blockIdx.y, b = blockIdx.z;
    const int m0 = mt * 64;
    const int kv = h >> 2;

    const __nv_bfloat16* qg = qr + ((size_t)(b * NH + h) * TT + m0) * HD;
    const __nv_bfloat16* kg = kr + ((size_t)(b * NKV + kv) * TT) * HD;
    const float*         vg = v  + ((size_t)b * TT) * KVDIM + kv * HD;

    for (int idx = tid; idx < 64 * 16; idx += 256) {
        int r  = idx >> 4;
        int d8 = (idx & 15) << 3;
        uint4 u = *(const uint4*)(qg + (size_t)r * HD + d8);
        const __nv_bfloat16* pb = (const __nv_bfloat16*)&u;
        #pragma unroll
        for (int j = 0; j < 8; j++)
            qs[r * 128 + d8 + j] = __bfloat162float(pb[j]);
    }

    float acc[32];
    #pragma unroll
    for (int j = 0; j < 32; j++) acc[j] = 0.f;
    float mrow = -1e30f, lrow = 0.f;

    const int r  = tid >> 2;
    const int cg = tid & 3;
    const int tx = tid & 15;
    const int ty = tid >> 4;

    const int ntile = mt + 1;
    for (int jt = 0; jt < ntile; jt++) {
        const int kn = jt * 64;
        __syncthreads();

        for (int idx = tid; idx < 64 * 16; idx += 256) {
            int n  = idx >> 4;
            int d8 = (idx & 15) << 3;
            uint4 u = *(const uint4*)(kg + (size_t)(kn + n) * HD + d8);
            const __nv_bfloat16* pb = (const __nv_bfloat16*)&u;
            #pragma unroll
            for (int j = 0; j < 8; j++)
                kst[(d8 + j) * 65 + n] = __bfloat162float(pb[j]);
        }
        for (int idx = tid; idx < 64 * 32; idx += 256) {
            int n  = idx >> 5;
            int c4 = (idx & 31) << 2;
            *(float4*)&vs[n * 128 + c4] =
                *(const float4*)(vg + (size_t)(kn + n) * KVDIM + c4);
        }
        __syncthreads();

        float sacc[4][4];
        #pragma unroll
        for (int i = 0; i < 4; i++)
            #pragma unroll
            for (int j = 0; j < 4; j++) sacc[i][j] = 0.f;

        #pragma unroll 4
        for (int d = 0; d < 128; d++) {
            float a0 = qs[(ty * 4 + 0) * 128 + d];
            float a1 = qs[(ty * 4 + 1) * 128 + d];
            float a2 = qs[(ty * 4 + 2) * 128 + d];
            float a3 = qs[(ty * 4 + 3) * 128 + d];
            float b0 = kst[d * 65 + tx * 4 + 0];
            float b1 = kst[d * 65 + tx * 4 + 1];
            float b2 = kst[d * 65 + tx * 4 + 2];
            float b3 = kst[d * 65 + tx * 4 + 3];
            sacc[0][0] += a0 * b0; sacc[0][1] += a0 * b1; sacc[0][2] += a0 * b2; sacc[0][3] += a0 * b3;
            sacc[1][0] += a1 * b0; sacc[1][1] += a1 * b1; sacc[1][2] += a1 * b2; sacc[1][3] += a1 * b3;
            sacc[2][0] += a2 * b0; sacc[2][1] += a2 * b1; sacc[2][2] += a2 * b2; sacc[2][3] += a2 * b3;
            sacc[3][0] += a3 * b0; sacc[3][1] += a3 * b1; sacc[3][2] += a3 * b2; sacc[3][3] += a3 * b3;
        }
        #pragma unroll
        for (int i = 0; i < 4; i++) {
            int gm = m0 + ty * 4 + i;
            #pragma unroll
            for (int j = 0; j < 4; j++) {
                int gn = kn + tx * 4 + j;
                ss[(ty * 4 + i) * 68 + tx * 4 + j] = (gn <= gm) ? sacc[i][j] : -1e30f;
            }
        }
        __syncthreads();

        float tmax = -1e30f;
        #pragma unroll 8
        for (int n = 0; n < 64; n++) tmax = fmaxf(tmax, ss[r * 68 + n]);
        float mnew  = fmaxf(mrow, tmax);
        float alpha = __expf(mrow - mnew);
        __syncthreads();

        #pragma unroll
        for (int n = cg * 16; n < cg * 16 + 16; n++)
            ss[r * 68 + n] = __expf(ss[r * 68 + n] - mnew);
        mrow = mnew;
        lrow *= alpha;
        #pragma unroll
        for (int j = 0; j < 32; j++) acc[j] *= alpha;
        __syncthreads();

        for (int n = 0; n < 64; n++) {
            float p = ss[r * 68 + n];
            lrow += p;
            #pragma unroll
            for (int j = 0; j < 32; j++)
                acc[j] += p * vs[n * 128 + cg + 4 * j];
        }
    }

    const float inv = 0.022097086912079608f / lrow;
    float* og = o + ((size_t)(b * TT + m0 + r)) * NE + h * HD + cg;
    #pragma unroll
    for (int j = 0; j < 32; j++)
        og[4 * j] = acc[j] * inv;
}

// ---------------------------------------------------------------------------
// launch
// ---------------------------------------------------------------------------
extern "C" void kernel_launch(void* const* d_in, const int* in_sizes, int n_in,
                              void* d_out, int out_size)
{
    const float* x  = (const float*)d_in[0];
    const float* Wq = (const float*)d_in[1];
    const float* bq = (const float*)d_in[2];
    const float* Wk = (const float*)d_in[3];
    const float* bk = (const float*)d_in[4];
    const float* Wv = (const float*)d_in[5];
    const float* bv = (const float*)d_in[6];
    const float* Wo = (const float*)d_in[7];
    const float* bo = (const float*)d_in[8];
    float* out = (float*)d_out;

    float *qb, *kb, *vb, *ob, *ct, *st;
    __nv_bfloat16 *qr, *kr;
    __nv_bfloat16 *xh, *xl, *oh, *ol;
    __nv_bfloat16 *wqh, *wql, *wkh, *wkl, *wvh, *wvl, *woh, *wol;
    cudaGetSymbolAddress((void**)&qb, g_q);
    cudaGetSymbolAddress((void**)&kb, g_k);
    cudaGetSymbolAddress((void**)&vb, g_v);
    cudaGetSymbolAddress((void**)&ob, g_o);
    cudaGetSymbolAddress((void**)&ct, g_cos);
    cudaGetSymbolAddress((void**)&st, g_sin);
    cudaGetSymbolAddress((void**)&qr, g_qr);
    cudaGetSymbolAddress((void**)&kr, g_kr);
    cudaGetSymbolAddress((void**)&xh, g_xh);
    cudaGetSymbolAddress((void**)&xl, g_xl);
    cudaGetSymbolAddress((void**)&oh, g_oh);
    cudaGetSymbolAddress((void**)&ol, g_ol);
    cudaGetSymbolAddress((void**)&wqh, g_wqh);
    cudaGetSymbolAddress((void**)&wql, g_wql);
    cudaGetSymbolAddress((void**)&wkh, g_wkh);
    cudaGetSymbolAddress((void**)&wkl, g_wkl);
    cudaGetSymbolAddress((void**)&wvh, g_wvh);
    cudaGetSymbolAddress((void**)&wvl, g_wvl);
    cudaGetSymbolAddress((void**)&woh, g_woh);
    cudaGetSymbolAddress((void**)&wol, g_wol);

    cudaFuncSetAttribute(gemm_mma_kernel, cudaFuncAttributeMaxDynamicSharedMemorySize, GEMM_SMEM);
    {
        size_t smem = (size_t)ATTN_SMEM_FLOATS * sizeof(float);
        cudaFuncSetAttribute(attn_kernel, cudaFuncAttributeMaxDynamicSharedMemorySize, (int)smem);
    }

    // prep: weight transposes + x split
    tsplit_kernel<<<dim3(NE / 32, NE / 32), 256>>>(Wq, wqh, wql, NE, NE);
    tsplit_kernel<<<dim3(KVDIM / 32, NE / 32), 256>>>(Wk, wkh, wkl, NE, KVDIM);
    tsplit_kernel<<<dim3(KVDIM / 32, NE / 32), 256>>>(Wv, wvh, wvl, NE, KVDIM);
    tsplit_kernel<<<dim3(NE / 32, NE / 32), 256>>>(Wo, woh, wol, NE, NE);
    split_kernel<<<(MROWS * NE / 8 + 255) / 256, 256>>>(x, xh, xl, MROWS * NE / 8);

    // projections on tensor cores (mma.sync)
    gemm_mma_kernel<<<dim3(NE / 128, MROWS / 128), 256, GEMM_SMEM>>>(
        xh, xl, wqh, wql, bq, qb, MROWS, NE, NE);
    gemm_mma_kernel<<<dim3(KVDIM / 128, MROWS / 128), 256, GEMM_SMEM>>>(
        xh, xl, wkh, wkl, bk, kb, MROWS, KVDIM, NE);
    gemm_mma_kernel<<<dim3(KVDIM / 128, MROWS / 128), 256, GEMM_SMEM>>>(
        xh, xl, wvh, wvl, bv, vb, MROWS, KVDIM, NE);

    // RoPE
    rope_table_kernel<<<(TT * 64 + 255) / 256, 256>>>(ct, st);
    rope_q_kernel<<<(BB * TT * NH * 64) / 256, 256>>>(qb, ct, st, qr);
    rope_k_kernel<<<(BB * TT * NKV * 64) / 256, 256>>>(kb, ct, st, kr);

    // attention
    {
        size_t smem = (size_t)ATTN_SMEM_FLOATS * sizeof(float);
        dim3 grid(TT / 64, NH, BB);
        attn_kernel<<<grid, 256, smem>>>(qr, kr, vb, ob);
    }

    // output projection
    split_kernel<<<(MROWS * NE / 8 + 255) / 256, 256>>>(ob, oh, ol, MROWS * NE / 8);
    gemm_mma_kernel<<<dim3(NE / 128, MROWS / 128), 256, GEMM_SMEM>>>(
        oh, ol, woh, wol, bo, out, MROWS, NE, NE);
}

// round 6
// speedup vs baseline: 3.8133x; 3.4524x over previous
#include <cuda_runtime.h>
#include <cuda_bf16.h>
#include <cstdint>
#include <cmath>

// ---------------------------------------------------------------------------
// Problem constants (fixed shapes)
// ---------------------------------------------------------------------------
#define BB 2
#define TT 2048
#define NE 2048          // N_EMBED
#define NH 16            // N_HEAD
#define NKV 4            // N_KV_HEAD
#define HD 128           // HEAD_DIM
#define MROWS (BB*TT)    // 4096
#define KVDIM (NKV*HD)   // 512

// ---------------------------------------------------------------------------
// Scratch (static device globals; no allocations allowed)
// ---------------------------------------------------------------------------
__device__ float g_q[(size_t)MROWS * NE];       // x@Wq+bq
__device__ float g_k[(size_t)MROWS * KVDIM];    // x@Wk+bk
__device__ float g_v[(size_t)MROWS * KVDIM];    // x@Wv+bv
__device__ float g_o[(size_t)MROWS * NE];       // attention output [B,T,H*D]
__device__ __nv_bfloat16 g_qr[(size_t)BB * NH * TT * HD];   // rope(q) bf16 [B,H,T,D]
__device__ __nv_bfloat16 g_kr[(size_t)BB * NKV * TT * HD];  // rope(k) bf16 [B,KV,T,D]
__device__ __nv_bfloat16 g_vh[(size_t)BB * NKV * TT * HD];  // v hi bf16 [B,KV,T,D]
__device__ __nv_bfloat16 g_vl[(size_t)BB * NKV * TT * HD];  // v lo bf16 [B,KV,T,D]
__device__ float g_cos[TT * (HD/2)];
__device__ float g_sin[TT * (HD/2)];

// split-bf16 operands for tensor-core GEMMs
__device__ __nv_bfloat16 g_xh[(size_t)MROWS * NE];
__device__ __nv_bfloat16 g_xl[(size_t)MROWS * NE];
__device__ __nv_bfloat16 g_oh[(size_t)MROWS * NE];
__device__ __nv_bfloat16 g_ol[(size_t)MROWS * NE];
// transposed weights [N][K], hi/lo
__device__ __nv_bfloat16 g_wqh[(size_t)NE * NE];
__device__ __nv_bfloat16 g_wql[(size_t)NE * NE];
__device__ __nv_bfloat16 g_wkh[(size_t)KVDIM * NE];
__device__ __nv_bfloat16 g_wkl[(size_t)KVDIM * NE];
__device__ __nv_bfloat16 g_wvh[(size_t)KVDIM * NE];
__device__ __nv_bfloat16 g_wvl[(size_t)KVDIM * NE];
__device__ __nv_bfloat16 g_woh[(size_t)NE * NE];
__device__ __nv_bfloat16 g_wol[(size_t)NE * NE];

// ---------------------------------------------------------------------------
// Helpers (baseline PTX only — no sm_103a-suffixed features)
// ---------------------------------------------------------------------------
__device__ __forceinline__ uint32_t smem_u32(const void* p) {
    uint32_t a;
    asm("{ .reg .u64 t; cvta.to.shared.u64 t, %1; cvt.u32.u64 %0, t; }" : "=r"(a) : "l"(p));
    return a;
}
__device__ __forceinline__ uint32_t sw128(uint32_t off) {
    return off ^ ((off >> 3) & 0x70);
}
__device__ __forceinline__ void cp16(uint32_t dst, const void* src) {
    asm volatile("cp.async.cg.shared.global [%0], [%1], 16;" :: "r"(dst), "l"(src) : "memory");
}
__device__ __forceinline__ void ldsm4(uint32_t* r, uint32_t addr) {
    asm volatile("ldmatrix.sync.aligned.m8n8.x4.shared.b16 {%0,%1,%2,%3}, [%4];"
                 : "=r"(r[0]), "=r"(r[1]), "=r"(r[2]), "=r"(r[3]) : "r"(addr));
}
__device__ __forceinline__ void ldsm4t(uint32_t* r, uint32_t addr) {
    asm volatile("ldmatrix.sync.aligned.m8n8.x4.trans.shared.b16 {%0,%1,%2,%3}, [%4];"
                 : "=r"(r[0]), "=r"(r[1]), "=r"(r[2]), "=r"(r[3]) : "r"(addr));
}
__device__ __forceinline__ void mma16816(float* c, const uint32_t* a, const uint32_t* b) {
    asm volatile(
        "mma.sync.aligned.m16n8k16.row.col.f32.bf16.bf16.f32 "
        "{%0,%1,%2,%3}, {%4,%5,%6,%7}, {%8,%9}, {%0,%1,%2,%3};"
        : "+f"(c[0]), "+f"(c[1]), "+f"(c[2]), "+f"(c[3])
        : "r"(a[0]), "r"(a[1]), "r"(a[2]), "r"(a[3]), "r"(b[0]), "r"(b[1]));
}
__device__ __forceinline__ uint32_t packbf2(__nv_bfloat16 lo, __nv_bfloat16 hi) {
    return ((uint32_t)__bfloat16_as_ushort(hi) << 16) | (uint32_t)__bfloat16_as_ushort(lo);
}

// ---------------------------------------------------------------------------
// Prep kernels: split fp32 -> hi/lo bf16; transpose+split weights
// ---------------------------------------------------------------------------
__global__ void __launch_bounds__(256)
split_kernel(const float* __restrict__ x, __nv_bfloat16* __restrict__ xh,
             __nv_bfloat16* __restrict__ xl, int n8)
{
    int i = blockIdx.x * 256 + threadIdx.x;
    if (i >= n8) return;
    size_t base = (size_t)i * 8;
    float4 v0 = *(const float4*)(x + base);
    float4 v1 = *(const float4*)(x + base + 4);
    float vv[8] = {v0.x, v0.y, v0.z, v0.w, v1.x, v1.y, v1.z, v1.w};
    union { __nv_bfloat16 b[8]; uint4 u; } ph, pl;
    #pragma unroll
    for (int j = 0; j < 8; j++) {
        __nv_bfloat16 h = __float2bfloat16(vv[j]);
        ph.b[j] = h;
        pl.b[j] = __float2bfloat16(vv[j] - __bfloat162float(h));
    }
    *(uint4*)(xh + base) = ph.u;
    *(uint4*)(xl + base) = pl.u;
}

// W[K][N] row-major -> Th/Tl[N][K] bf16
__global__ void __launch_bounds__(256)
tsplit_kernel(const float* __restrict__ W, __nv_bfloat16* __restrict__ Th,
              __nv_bfloat16* __restrict__ Tl, int K, int N)
{
    __shared__ float t[32][33];
    int n0 = blockIdx.x * 32, k0 = blockIdx.y * 32;
    int tx = threadIdx.x & 31, ty = threadIdx.x >> 5;   // 32x8
    #pragma unroll
    for (int i = 0; i < 4; i++)
        t[ty + i * 8][tx] = W[(size_t)(k0 + ty + i * 8) * N + n0 + tx];
    __syncthreads();
    #pragma unroll
    for (int i = 0; i < 4; i++) {
        int n = n0 + ty + i * 8, k = k0 + tx;
        float v = t[tx][ty + i * 8];
        __nv_bfloat16 h = __float2bfloat16(v);
        Th[(size_t)n * K + k] = h;
        Tl[(size_t)n * K + k] = __float2bfloat16(v - __bfloat162float(h));
    }
}

// v [B,T,KV*HD] fp32 -> vh/vl [B,KV,T,HD] bf16 hi/lo
__global__ void __launch_bounds__(256)
vsplit_kernel(const float* __restrict__ v, __nv_bfloat16* __restrict__ vh,
              __nv_bfloat16* __restrict__ vl)
{
    int idx = blockIdx.x * 256 + threadIdx.x;   // total BB*TT*NKV*32
    int c  = idx & 31;            // d quad
    int kv = (idx >> 5) & 3;
    int t  = (idx >> 7) & 2047;
    int b  = idx >> 18;
    int d  = c << 2;
    float4 vv = *(const float4*)(v + ((size_t)(b * TT + t)) * KVDIM + kv * HD + d);
    float f[4] = {vv.x, vv.y, vv.z, vv.w};
    union { __nv_bfloat16 b4[4]; uint2 u; } hh, ll;
    #pragma unroll
    for (int j = 0; j < 4; j++) {
        __nv_bfloat16 h = __float2bfloat16(f[j]);
        hh.b4[j] = h;
        ll.b4[j] = __float2bfloat16(f[j] - __bfloat162float(h));
    }
    size_t dst = ((size_t)((b * NKV + kv) * TT) + t) * HD + d;
    *(uint2*)(vh + dst) = hh.u;
    *(uint2*)(vl + dst) = ll.u;
}

// ---------------------------------------------------------------------------
// mma.sync split-bf16 GEMM: C[M,N] = Ah@Bh^T + Ah@Bl^T + Al@Bh^T + bias
// BM=128, BN=128, BK=64, 256 threads (4m x 2n warps), 3-stage cp.async.
// Stage layout: Ah@0 | Al@16K | Bh@32K | Bl@48K  (each 128 rows x 128B, SW128)
// ---------------------------------------------------------------------------
#define STG_BYTES 65536
#define GEMM_SMEM (3*STG_BYTES + 1024)

__global__ void __launch_bounds__(256, 1)
gemm_mma_kernel(const __nv_bfloat16* __restrict__ Ah, const __nv_bfloat16* __restrict__ Al,
                const __nv_bfloat16* __restrict__ BTh, const __nv_bfloat16* __restrict__ BTl,
                const float* __restrict__ bias, float* __restrict__ C,
                int M, int N, int K)
{
    extern __shared__ char dsm[];
    char* smbase = (char*)(((uintptr_t)dsm + 1023) & ~(uintptr_t)1023);
    const uint32_t sb = smem_u32(smbase);

    const int tid  = threadIdx.x;
    const int lane = tid & 31;
    const int wid  = tid >> 5;
    const int wm   = wid >> 1;          // 0..3
    const int wn   = wid & 1;           // 0..1
    const int m0   = blockIdx.y * 128;
    const int n0   = blockIdx.x * 128;

    const int nstage = K / 64;

    float c[2][8][4];
    #pragma unroll
    for (int im = 0; im < 2; im++)
        #pragma unroll
        for (int in = 0; in < 8; in++)
            #pragma unroll
            for (int j = 0; j < 4; j++) c[im][in][j] = 0.f;

    auto load_stage = [&](int s) {
        const int k0 = s * 64;
        const uint32_t stg = sb + (uint32_t)(s % 3) * STG_BYTES;
        #pragma unroll
        for (int i = 0; i < 16; i++) {
            int idx = tid + (i << 8);
            int tl  = idx >> 10;            // 0:Ah 1:Al 2:Bh 3:Bl
            int row = (idx >> 3) & 127;
            int q   = idx & 7;
            const __nv_bfloat16* src;
            if (tl == 0)      src = Ah  + (size_t)(m0 + row) * K + k0 + q * 8;
            else if (tl == 1) src = Al  + (size_t)(m0 + row) * K + k0 + q * 8;
            else if (tl == 2) src = BTh + (size_t)(n0 + row) * K + k0 + q * 8;
            else              src = BTl + (size_t)(n0 + row) * K + k0 + q * 8;
            cp16(stg + tl * 16384 + sw128((uint32_t)(row * 128 + q * 16)), src);
        }
    };

    load_stage(0);
    asm volatile("cp.async.commit_group;" ::: "memory");
    load_stage(1);
    asm volatile("cp.async.commit_group;" ::: "memory");

    const int aRow  = (lane & 15);
    const int aKoff = (lane >> 4) << 4;
    const int bRow  = (lane & 7) + ((lane >> 4) << 3);
    const int bKoff = ((lane >> 3) & 1) << 4;

    for (int s = 0; s < nstage; s++) {
        if (s + 2 < nstage) {
            load_stage(s + 2);
            asm volatile("cp.async.commit_group;" ::: "memory");
            asm volatile("cp.async.wait_group 2;" ::: "memory");
        } else if (s + 1 < nstage) {
            asm volatile("cp.async.wait_group 1;" ::: "memory");
        } else {
            asm volatile("cp.async.wait_group 0;" ::: "memory");
        }
        __syncthreads();

        const uint32_t ab = sb + (uint32_t)(s % 3) * STG_BYTES;

        #pragma unroll
        for (int kk = 0; kk < 4; kk++) {
            const int kb = kk * 32;
            uint32_t a_h[2][4], a_l[2][4];
            #pragma unroll
            for (int im = 0; im < 2; im++) {
                uint32_t off = sw128((uint32_t)((wm * 32 + im * 16 + aRow) * 128 + kb + aKoff));
                ldsm4(a_h[im], ab + off);
                ldsm4(a_l[im], ab + 16384 + off);
            }
            uint32_t b_h[16], b_l[16];
            #pragma unroll
            for (int ib = 0; ib < 4; ib++) {
                uint32_t off = sw128((uint32_t)((wn * 64 + ib * 16 + bRow) * 128 + kb + bKoff));
                ldsm4(&b_h[ib * 4], ab + 32768 + off);
                ldsm4(&b_l[ib * 4], ab + 49152 + off);
            }
            #pragma unroll
            for (int im = 0; im < 2; im++) {
                #pragma unroll
                for (int in = 0; in < 8; in++) {
                    const uint32_t* bh = &b_h[(in >> 1) * 4 + (in & 1) * 2];
                    const uint32_t* bl = &b_l[(in >> 1) * 4 + (in & 1) * 2];
                    mma16816(c[im][in], a_h[im], bh);
                    mma16816(c[im][in], a_l[im], bh);
                    mma16816(c[im][in], a_h[im], bl);
                }
            }
        }
        __syncthreads();
    }

    // epilogue: add bias, store fp32
    #pragma unroll
    for (int im = 0; im < 2; im++) {
        const int r0 = m0 + wm * 32 + im * 16 + (lane >> 2);
        #pragma unroll
        for (int in = 0; in < 8; in++) {
            const int cc = n0 + wn * 64 + in * 8 + ((lane & 3) << 1);
            float2 bb = *(const float2*)&bias[cc];
            float2 o0, o1;
            o0.x = c[im][in][0] + bb.x;  o0.y = c[im][in][1] + bb.y;
            o1.x = c[im][in][2] + bb.x;  o1.y = c[im][in][3] + bb.y;
            *(float2*)&C[(size_t)r0 * N + cc]       = o0;
            *(float2*)&C[(size_t)(r0 + 8) * N + cc] = o1;
        }
    }
}

// ---------------------------------------------------------------------------
// RoPE table: angle = fp32(t) * fp32(double-precision freq)
// ---------------------------------------------------------------------------
__global__ void __launch_bounds__(256)
rope_table_kernel(float* __restrict__ ct, float* __restrict__ st)
{
    int idx = blockIdx.x * 256 + threadIdx.x;
    if (idx >= TT * (HD/2)) return;
    int t = idx >> 6;
    int i = idx & 63;
    double fr = exp(-((double)(2 * i) / (double)NE) * log(10000.0));
    float ff = (float)fr;
    float ang = __fmul_rn((float)t, ff);
    float s, c;
    sincosf(ang, &s, &c);
    ct[idx] = c;
    st[idx] = s;
}

__global__ void __launch_bounds__(256)
rope_q_kernel(const float* __restrict__ q, const float* __restrict__ ct,
              const float* __restrict__ st, __nv_bfloat16* __restrict__ qr)
{
    int idx = blockIdx.x * 256 + threadIdx.x;
    int i = idx & 63;
    int h = (idx >> 6) & 15;
    int t = (idx >> 10) & 2047;
    int b = idx >> 21;
    size_t src = ((size_t)(b * TT + t)) * NE + h * HD + 2 * i;
    float xr = q[src], xi = q[src + 1];
    float c = ct[t * 64 + i], s = st[t * 64 + i];
    float orr = xr * c - xi * s;
    float oii = xr * s + xi * c;
    size_t dst = ((size_t)((b * NH + h) * TT + t)) * HD + 2 * i;
    qr[dst]     = __float2bfloat16(orr);
    qr[dst + 1] = __float2bfloat16(oii);
}

__global__ void __launch_bounds__(256)
rope_k_kernel(const float* __restrict__ k, const float* __restrict__ ct,
              const float* __restrict__ st, __nv_bfloat16* __restrict__ kr)
{
    int idx = blockIdx.x * 256 + threadIdx.x;
    int i = idx & 63;
    int h = (idx >> 6) & 3;
    int t = (idx >> 8) & 2047;
    int b = idx >> 19;
    size_t src = ((size_t)(b * TT + t)) * KVDIM + h * HD + 2 * i;
    float xr = k[src], xi = k[src + 1];
    float c = ct[t * 64 + i], s = st[t * 64 + i];
    float orr = xr * c - xi * s;
    float oii = xr * s + xi * c;
    size_t dst = ((size_t)((b * NKV + h) * TT + t)) * HD + 2 * i;
    kr[dst]     = __float2bfloat16(orr);
    kr[dst + 1] = __float2bfloat16(oii);
}

// ---------------------------------------------------------------------------
// Flash attention (causal, GQA) on mma.sync. BM=64, BN=64, 128 threads/4 warps.
// q,k bf16 exact; S=QK^T fp32 accum; online softmax in registers;
// AV = ph@vh + pl@vh + ph@vl (split-bf16), O fp32 accum in registers.
// smem rows padded to 272B for conflict-free ldmatrix.
// ---------------------------------------------------------------------------
#define AT_RS 272
#define AT_TILE (64 * AT_RS)
#define ATT_SMEM (7 * AT_TILE + 1024)

__global__ void __launch_bounds__(128, 1)
attn_mma_kernel(const __nv_bfloat16* __restrict__ qr, const __nv_bfloat16* __restrict__ kr,
                const __nv_bfloat16* __restrict__ vh, const __nv_bfloat16* __restrict__ vl,
                float* __restrict__ o)
{
    extern __shared__ char dsm2[];
    char* smb = (char*)(((uintptr_t)dsm2 + 1023) & ~(uintptr_t)1023);
    const uint32_t sb = smem_u32(smb);

    const int tid  = threadIdx.x;
    const int lane = tid & 31;
    const int w    = tid >> 5;
    const int mt   = (int)gridDim.x - 1 - (int)blockIdx.x;   // heavy blocks first
    const int h    = blockIdx.y, b = blockIdx.z;
    const int m0   = mt * 64;
    const int kv   = h >> 2;

    const __nv_bfloat16* qg  = qr + ((size_t)(b * NH + h) * TT + m0) * HD;
    const __nv_bfloat16* kg  = kr + ((size_t)(b * NKV + kv) * TT) * HD;
    const __nv_bfloat16* vhg = vh + ((size_t)(b * NKV + kv) * TT) * HD;
    const __nv_bfloat16* vlg = vl + ((size_t)(b * NKV + kv) * TT) * HD;

    // smem: Q | {K,Vh,Vl} x 2 buffers
    const uint32_t Q0 = sb;
    auto toff = [&](int buf, int which) -> uint32_t {
        return sb + (uint32_t)AT_TILE * (1 + buf * 3 + which);
    };
    auto load64 = [&](uint32_t dst, const __nv_bfloat16* src) {
        #pragma unroll
        for (int i = 0; i < 8; i++) {
            int idx = tid + i * 128;
            int row = idx >> 4, cq = idx & 15;
            cp16(dst + (uint32_t)(row * AT_RS + cq * 16), src + (size_t)row * HD + cq * 8);
        }
    };

    load64(Q0, qg);
    load64(toff(0, 0), kg);
    load64(toff(0, 1), vhg);
    load64(toff(0, 2), vlg);
    asm volatile("cp.async.commit_group;" ::: "memory");

    uint32_t qf[8][4];
    float ov[16][4];
    #pragma unroll
    for (int n = 0; n < 16; n++) { ov[n][0] = ov[n][1] = ov[n][2] = ov[n][3] = 0.f; }
    float m_lo = -1e30f, m_hi = -1e30f, l_lo = 0.f, l_hi = 0.f;

    const int aRow = lane & 15;
    const int aK   = (lane >> 4) << 4;
    const int bRow = (lane & 7) + ((lane >> 4) << 3);
    const int bK   = ((lane >> 3) & 1) << 4;
    const int vRow = (lane & 7) + (((lane >> 3) & 1) << 3);
    const int vC   = (lane >> 4) << 4;

    for (int jt = 0; jt <= mt; jt++) {
        if (jt < mt) {
            int nb = (jt + 1) & 1;
            load64(toff(nb, 0), kg  + (size_t)(jt + 1) * 64 * HD);
            load64(toff(nb, 1), vhg + (size_t)(jt + 1) * 64 * HD);
            load64(toff(nb, 2), vlg + (size_t)(jt + 1) * 64 * HD);
            asm volatile("cp.async.commit_group;" ::: "memory");
            asm volatile("cp.async.wait_group 1;" ::: "memory");
        } else {
            asm volatile("cp.async.wait_group 0;" ::: "memory");
        }
        __syncthreads();

        if (jt == 0) {
            #pragma unroll
            for (int kt = 0; kt < 8; kt++)
                ldsm4(qf[kt], Q0 + (uint32_t)((w * 16 + aRow) * AT_RS + kt * 32 + aK));
        }

        const uint32_t kb  = toff(jt & 1, 0);
        const uint32_t vhb = toff(jt & 1, 1);
        const uint32_t vlb = toff(jt & 1, 2);

        // ---- S = Q @ K^T ----
        float sc[8][4];
        #pragma unroll
        for (int j = 0; j < 8; j++) { sc[j][0] = sc[j][1] = sc[j][2] = sc[j][3] = 0.f; }

        #pragma unroll
        for (int kt = 0; kt < 8; kt++) {
            #pragma unroll
            for (int ib = 0; ib < 4; ib++) {
                uint32_t bf[4];
                ldsm4(bf, kb + (uint32_t)((ib * 16 + bRow) * AT_RS + kt * 32 + bK));
                mma16816(sc[2 * ib],     qf[kt], bf);
                mma16816(sc[2 * ib + 1], qf[kt], bf + 2);
            }
        }

        // ---- causal mask (diagonal tile only) ----
        if (jt == mt) {
            const int rl = w * 16 + (lane >> 2);
            #pragma unroll
            for (int j = 0; j < 8; j++) {
                int gn = j * 8 + ((lane & 3) << 1);
                if (gn     > rl)     sc[j][0] = -1e30f;
                if (gn + 1 > rl)     sc[j][1] = -1e30f;
                if (gn     > rl + 8) sc[j][2] = -1e30f;
                if (gn + 1 > rl + 8) sc[j][3] = -1e30f;
            }
        }

        // ---- online softmax ----
        float vlo = -1e30f, vhi = -1e30f;
        #pragma unroll
        for (int j = 0; j < 8; j++) {
            vlo = fmaxf(vlo, fmaxf(sc[j][0], sc[j][1]));
            vhi = fmaxf(vhi, fmaxf(sc[j][2], sc[j][3]));
        }
        vlo = fmaxf(vlo, __shfl_xor_sync(0xffffffffu, vlo, 1));
        vlo = fmaxf(vlo, __shfl_xor_sync(0xffffffffu, vlo, 2));
        vhi = fmaxf(vhi, __shfl_xor_sync(0xffffffffu, vhi, 1));
        vhi = fmaxf(vhi, __shfl_xor_sync(0xffffffffu, vhi, 2));
        float mn_lo = fmaxf(m_lo, vlo), mn_hi = fmaxf(m_hi, vhi);
        float al_lo = __expf(m_lo - mn_lo), al_hi = __expf(m_hi - mn_hi);
        m_lo = mn_lo; m_hi = mn_hi;
        l_lo *= al_lo; l_hi *= al_hi;
        #pragma unroll
        for (int n = 0; n < 16; n++) {
            ov[n][0] *= al_lo; ov[n][1] *= al_lo;
            ov[n][2] *= al_hi; ov[n][3] *= al_hi;
        }

        uint32_t ph[8][2], pl[8][2];
        #pragma unroll
        for (int j = 0; j < 8; j++) {
            float p0 = __expf(sc[j][0] - m_lo), p1 = __expf(sc[j][1] - m_lo);
            float p2 = __expf(sc[j][2] - m_hi), p3 = __expf(sc[j][3] - m_hi);
            l_lo += p0 + p1;  l_hi += p2 + p3;
            __nv_bfloat16 h0 = __float2bfloat16(p0), h1 = __float2bfloat16(p1);
            __nv_bfloat16 h2 = __float2bfloat16(p2), h3 = __float2bfloat16(p3);
            ph[j][0] = packbf2(h0, h1);
            ph[j][1] = packbf2(h2, h3);
            __nv_bfloat16 d0 = __float2bfloat16(p0 - __bfloat162float(h0));
            __nv_bfloat16 d1 = __float2bfloat16(p1 - __bfloat162float(h1));
            __nv_bfloat16 d2 = __float2bfloat16(p2 - __bfloat162float(h2));
            __nv_bfloat16 d3 = __float2bfloat16(p3 - __bfloat162float(h3));
            pl[j][0] = packbf2(d0, d1);
            pl[j][1] = packbf2(d2, d3);
        }

        // ---- O += P @ V  (3-term split) ----
        #pragma unroll
        for (int kt = 0; kt < 4; kt++) {
            uint32_t ah[4] = { ph[2*kt][0], ph[2*kt][1], ph[2*kt+1][0], ph[2*kt+1][1] };
            uint32_t am[4] = { pl[2*kt][0], pl[2*kt][1], pl[2*kt+1][0], pl[2*kt+1][1] };
            #pragma unroll
            for (int np = 0; np < 4; np++) {   // pairs of 16-d chunks (32 d)
                uint32_t base = (uint32_t)((kt * 16 + vRow) * AT_RS + np * 64 + vC);
                uint32_t bh0[4], bh1[4], bl0[4], bl1[4];
                ldsm4t(bh0, vhb + base);
                ldsm4t(bh1, vhb + base + 32);
                ldsm4t(bl0, vlb + base);
                ldsm4t(bl1, vlb + base + 32);
                mma16816(ov[np*4+0], ah, bh0);
                mma16816(ov[np*4+1], ah, bh0 + 2);
                mma16816(ov[np*4+2], ah, bh1);
                mma16816(ov[np*4+3], ah, bh1 + 2);
                mma16816(ov[np*4+0], am, bh0);
                mma16816(ov[np*4+1], am, bh0 + 2);
                mma16816(ov[np*4+2], am, bh1);
                mma16816(ov[np*4+3], am, bh1 + 2);
                mma16816(ov[np*4+0], ah, bl0);
                mma16816(ov[np*4+1], ah, bl0 + 2);
                mma16816(ov[np*4+2], ah, bl1);
                mma16816(ov[np*4+3], ah, bl1 + 2);
            }
        }
        __syncthreads();
    }

    // ---- epilogue ----
    l_lo += __shfl_xor_sync(0xffffffffu, l_lo, 1);
    l_lo += __shfl_xor_sync(0xffffffffu, l_lo, 2);
    l_hi += __shfl_xor_sync(0xffffffffu, l_hi, 1);
    l_hi += __shfl_xor_sync(0xffffffffu, l_hi, 2);
    const float inv_lo = 0.022097086912079608f / l_lo;
    const float inv_hi = 0.022097086912079608f / l_hi;
    const int rlo = m0 + w * 16 + (lane >> 2);
    float* og = o + ((size_t)(b * TT) + rlo) * NE + h * HD;
    #pragma unroll
    for (int n = 0; n < 16; n++) {
        int d = n * 8 + ((lane & 3) << 1);
        float2 x0 = { ov[n][0] * inv_lo, ov[n][1] * inv_lo };
        float2 x1 = { ov[n][2] * inv_hi, ov[n][3] * inv_hi };
        *(float2*)(og + d)          = x0;
        *(float2*)(og + 8 * NE + d) = x1;
    }
}

// ---------------------------------------------------------------------------
// launch
// ---------------------------------------------------------------------------
extern "C" void kernel_launch(void* const* d_in, const int* in_sizes, int n_in,
                              void* d_out, int out_size)
{
    const float* x  = (const float*)d_in[0];
    const float* Wq = (const float*)d_in[1];
    const float* bq = (const float*)d_in[2];
    const float* Wk = (const float*)d_in[3];
    const float* bk = (const float*)d_in[4];
    const float* Wv = (const float*)d_in[5];
    const float* bv = (const float*)d_in[6];
    const float* Wo = (const float*)d_in[7];
    const float* bo = (const float*)d_in[8];
    float* out = (float*)d_out;

    float *qb, *kb, *vb, *ob, *ct, *st;
    __nv_bfloat16 *qr, *kr, *vhp, *vlp;
    __nv_bfloat16 *xh, *xl, *oh, *ol;
    __nv_bfloat16 *wqh, *wql, *wkh, *wkl, *wvh, *wvl, *woh, *wol;
    cudaGetSymbolAddress((void**)&qb, g_q);
    cudaGetSymbolAddress((void**)&kb, g_k);
    cudaGetSymbolAddress((void**)&vb, g_v);
    cudaGetSymbolAddress((void**)&ob, g_o);
    cudaGetSymbolAddress((void**)&ct, g_cos);
    cudaGetSymbolAddress((void**)&st, g_sin);
    cudaGetSymbolAddress((void**)&qr, g_qr);
    cudaGetSymbolAddress((void**)&kr, g_kr);
    cudaGetSymbolAddress((void**)&vhp, g_vh);
    cudaGetSymbolAddress((void**)&vlp, g_vl);
    cudaGetSymbolAddress((void**)&xh, g_xh);
    cudaGetSymbolAddress((void**)&xl, g_xl);
    cudaGetSymbolAddress((void**)&oh, g_oh);
    cudaGetSymbolAddress((void**)&ol, g_ol);
    cudaGetSymbolAddress((void**)&wqh, g_wqh);
    cudaGetSymbolAddress((void**)&wql, g_wql);
    cudaGetSymbolAddress((void**)&wkh, g_wkh);
    cudaGetSymbolAddress((void**)&wkl, g_wkl);
    cudaGetSymbolAddress((void**)&wvh, g_wvh);
    cudaGetSymbolAddress((void**)&wvl, g_wvl);
    cudaGetSymbolAddress((void**)&woh, g_woh);
    cudaGetSymbolAddress((void**)&wol, g_wol);

    cudaFuncSetAttribute(gemm_mma_kernel, cudaFuncAttributeMaxDynamicSharedMemorySize, GEMM_SMEM);
    cudaFuncSetAttribute(attn_mma_kernel, cudaFuncAttributeMaxDynamicSharedMemorySize, ATT_SMEM);

    // prep: weight transposes + x split
    tsplit_kernel<<<dim3(NE / 32, NE / 32), 256>>>(Wq, wqh, wql, NE, NE);
    tsplit_kernel<<<dim3(KVDIM / 32, NE / 32), 256>>>(Wk, wkh, wkl, NE, KVDIM);
    tsplit_kernel<<<dim3(KVDIM / 32, NE / 32), 256>>>(Wv, wvh, wvl, NE, KVDIM);
    tsplit_kernel<<<dim3(NE / 32, NE / 32), 256>>>(Wo, woh, wol, NE, NE);
    split_kernel<<<(MROWS * NE / 8 + 255) / 256, 256>>>(x, xh, xl, MROWS * NE / 8);

    // projections on tensor cores (mma.sync)
    gemm_mma_kernel<<<dim3(NE / 128, MROWS / 128), 256, GEMM_SMEM>>>(
        xh, xl, wqh, wql, bq, qb, MROWS, NE, NE);
    gemm_mma_kernel<<<dim3(KVDIM / 128, MROWS / 128), 256, GEMM_SMEM>>>(
        xh, xl, wkh, wkl, bk, kb, MROWS, KVDIM, NE);
    gemm_mma_kernel<<<dim3(KVDIM / 128, MROWS / 128), 256, GEMM_SMEM>>>(
        xh, xl, wvh, wvl, bv, vb, MROWS, KVDIM, NE);

    // RoPE + V split
    rope_table_kernel<<<(TT * 64 + 255) / 256, 256>>>(ct, st);
    rope_q_kernel<<<(BB * TT * NH * 64) / 256, 256>>>(qb, ct, st, qr);
    rope_k_kernel<<<(BB * TT * NKV * 64) / 256, 256>>>(kb, ct, st, kr);
    vsplit_kernel<<<(BB * TT * NKV * 32) / 256, 256>>>(vb, vhp, vlp);

    // attention on tensor cores
    {
        dim3 grid(TT / 64, NH, BB);
        attn_mma_kernel<<<grid, 128, ATT_SMEM>>>(qr, kr, vhp, vlp, ob);
    }

    // output projection
    split_kernel<<<(MROWS * NE / 8 + 255) / 256, 256>>>(ob, oh, ol, MROWS * NE / 8);
    gemm_mma_kernel<<<dim3(NE / 128, MROWS / 128), 256, GEMM_SMEM>>>(
        oh, ol, woh, wol, bo, out, MROWS, NE, NE);
}

// round 7
// speedup vs baseline: 4.0085x; 1.0512x over previous
#include <cuda_runtime.h>
#include <cuda_bf16.h>
#include <cstdint>
#include <cmath>

// ---------------------------------------------------------------------------
// Problem constants (fixed shapes)
// ---------------------------------------------------------------------------
#define BB 2
#define TT 2048
#define NE 2048          // N_EMBED
#define NH 16            // N_HEAD
#define NKV 4            // N_KV_HEAD
#define HD 128           // HEAD_DIM
#define MROWS (BB*TT)    // 4096
#define KVDIM (NKV*HD)   // 512
#define NQKV (NE + 2*KVDIM)   // 3072

// ---------------------------------------------------------------------------
// Scratch (static device globals; no allocations allowed)
// ---------------------------------------------------------------------------
__device__ __nv_bfloat16 g_qr[(size_t)BB * NH * TT * HD];   // rope(q) bf16 [B,H,T,D]
__device__ __nv_bfloat16 g_kr[(size_t)BB * NKV * TT * HD];  // rope(k) bf16 [B,KV,T,D]
__device__ __nv_bfloat16 g_vh[(size_t)BB * NKV * TT * HD];  // v hi bf16 [B,KV,T,D]
__device__ __nv_bfloat16 g_vl[(size_t)BB * NKV * TT * HD];  // v lo bf16 [B,KV,T,D]
__device__ float g_cos[TT * (HD/2)];
__device__ float g_sin[TT * (HD/2)];

// split-bf16 operands for tensor-core GEMMs
__device__ __nv_bfloat16 g_xh[(size_t)MROWS * NE];
__device__ __nv_bfloat16 g_xl[(size_t)MROWS * NE];
__device__ __nv_bfloat16 g_oh[(size_t)MROWS * NE];   // attn out hi
__device__ __nv_bfloat16 g_ol[(size_t)MROWS * NE];   // attn out lo
// packed transposed weights [N][K] hi/lo: rows 0..2047 Wq^T, 2048..2559 Wk^T, 2560..3071 Wv^T
__device__ __nv_bfloat16 g_wqkvh[(size_t)NQKV * NE];
__device__ __nv_bfloat16 g_wqkvl[(size_t)NQKV * NE];
__device__ __nv_bfloat16 g_woh[(size_t)NE * NE];
__device__ __nv_bfloat16 g_wol[(size_t)NE * NE];

// ---------------------------------------------------------------------------
// Helpers (baseline PTX only — no sm_103a-suffixed features)
// ---------------------------------------------------------------------------
__device__ __forceinline__ uint32_t smem_u32(const void* p) {
    uint32_t a;
    asm("{ .reg .u64 t; cvta.to.shared.u64 t, %1; cvt.u32.u64 %0, t; }" : "=r"(a) : "l"(p));
    return a;
}
__device__ __forceinline__ uint32_t sw128(uint32_t off) {
    return off ^ ((off >> 3) & 0x70);
}
__device__ __forceinline__ void cp16(uint32_t dst, const void* src) {
    asm volatile("cp.async.cg.shared.global [%0], [%1], 16;" :: "r"(dst), "l"(src) : "memory");
}
__device__ __forceinline__ void ldsm4(uint32_t* r, uint32_t addr) {
    asm volatile("ldmatrix.sync.aligned.m8n8.x4.shared.b16 {%0,%1,%2,%3}, [%4];"
                 : "=r"(r[0]), "=r"(r[1]), "=r"(r[2]), "=r"(r[3]) : "r"(addr));
}
__device__ __forceinline__ void ldsm4t(uint32_t* r, uint32_t addr) {
    asm volatile("ldmatrix.sync.aligned.m8n8.x4.trans.shared.b16 {%0,%1,%2,%3}, [%4];"
                 : "=r"(r[0]), "=r"(r[1]), "=r"(r[2]), "=r"(r[3]) : "r"(addr));
}
__device__ __forceinline__ void mma16816(float* c, const uint32_t* a, const uint32_t* b) {
    asm volatile(
        "mma.sync.aligned.m16n8k16.row.col.f32.bf16.bf16.f32 "
        "{%0,%1,%2,%3}, {%4,%5,%6,%7}, {%8,%9}, {%0,%1,%2,%3};"
        : "+f"(c[0]), "+f"(c[1]), "+f"(c[2]), "+f"(c[3])
        : "r"(a[0]), "r"(a[1]), "r"(a[2]), "r"(a[3]), "r"(b[0]), "r"(b[1]));
}
__device__ __forceinline__ uint32_t packbf2(__nv_bfloat16 lo, __nv_bfloat16 hi) {
    return ((uint32_t)__bfloat16_as_ushort(hi) << 16) | (uint32_t)__bfloat16_as_ushort(lo);
}

// ---------------------------------------------------------------------------
// Prep kernels
// ---------------------------------------------------------------------------
__global__ void __launch_bounds__(256)
split_kernel(const float* __restrict__ x, __nv_bfloat16* __restrict__ xh,
             __nv_bfloat16* __restrict__ xl, int n8)
{
    int i = blockIdx.x * 256 + threadIdx.x;
    if (i >= n8) return;
    size_t base = (size_t)i * 8;
    float4 v0 = *(const float4*)(x + base);
    float4 v1 = *(const float4*)(x + base + 4);
    float vv[8] = {v0.x, v0.y, v0.z, v0.w, v1.x, v1.y, v1.z, v1.w};
    union { __nv_bfloat16 b[8]; uint4 u; } ph, pl;
    #pragma unroll
    for (int j = 0; j < 8; j++) {
        __nv_bfloat16 h = __float2bfloat16(vv[j]);
        ph.b[j] = h;
        pl.b[j] = __float2bfloat16(vv[j] - __bfloat162float(h));
    }
    *(uint4*)(xh + base) = ph.u;
    *(uint4*)(xl + base) = pl.u;
}

// W[K][N] row-major -> Th/Tl[N][K] bf16
__global__ void __launch_bounds__(256)
tsplit_kernel(const float* __restrict__ W, __nv_bfloat16* __restrict__ Th,
              __nv_bfloat16* __restrict__ Tl, int K, int N)
{
    __shared__ float t[32][33];
    int n0 = blockIdx.x * 32, k0 = blockIdx.y * 32;
    int tx = threadIdx.x & 31, ty = threadIdx.x >> 5;   // 32x8
    #pragma unroll
    for (int i = 0; i < 4; i++)
        t[ty + i * 8][tx] = W[(size_t)(k0 + ty + i * 8) * N + n0 + tx];
    __syncthreads();
    #pragma unroll
    for (int i = 0; i < 4; i++) {
        int n = n0 + ty + i * 8, k = k0 + tx;
        float v = t[tx][ty + i * 8];
        __nv_bfloat16 h = __float2bfloat16(v);
        Th[(size_t)n * K + k] = h;
        Tl[(size_t)n * K + k] = __float2bfloat16(v - __bfloat162float(h));
    }
}

// RoPE table: angle = fp32(t) * fp32(double-precision freq)
__global__ void __launch_bounds__(256)
rope_table_kernel(float* __restrict__ ct, float* __restrict__ st)
{
    int idx = blockIdx.x * 256 + threadIdx.x;
    if (idx >= TT * (HD/2)) return;
    int t = idx >> 6;
    int i = idx & 63;
    double fr = exp(-((double)(2 * i) / (double)NE) * log(10000.0));
    float ff = (float)fr;
    float ang = __fmul_rn((float)t, ff);
    float s, c;
    sincosf(ang, &s, &c);
    ct[idx] = c;
    st[idx] = s;
}

// ---------------------------------------------------------------------------
// GEMM core: split-bf16 C = Ah@Bh^T + Ah@Bl^T + Al@Bh^T
// BM=128, BN=128, BK=64, 256 threads (4m x 2n warps), 3-stage cp.async.
// Stage layout: Ah@0 | Al@16K | Bh@32K | Bl@48K (each 128 rows x 128B, SW128)
// ---------------------------------------------------------------------------
#define STG_BYTES 65536
#define GEMM_SMEM (3*STG_BYTES + 1024)

__device__ __forceinline__ void gemm_core(
    const __nv_bfloat16* __restrict__ Ah, const __nv_bfloat16* __restrict__ Al,
    const __nv_bfloat16* __restrict__ BTh, const __nv_bfloat16* __restrict__ BTl,
    int K, int m0, int n0, uint32_t sb, int tid, float c[2][8][4])
{
    const int lane = tid & 31;
    const int wm   = (tid >> 5) >> 1;
    const int wn   = (tid >> 5) & 1;
    const int nstage = K / 64;

    #pragma unroll
    for (int im = 0; im < 2; im++)
        #pragma unroll
        for (int in = 0; in < 8; in++)
            #pragma unroll
            for (int j = 0; j < 4; j++) c[im][in][j] = 0.f;

    auto load_stage = [&](int s) {
        const int k0 = s * 64;
        const uint32_t stg = sb + (uint32_t)(s % 3) * STG_BYTES;
        #pragma unroll
        for (int i = 0; i < 16; i++) {
            int idx = tid + (i << 8);
            int tl  = idx >> 10;            // 0:Ah 1:Al 2:Bh 3:Bl
            int row = (idx >> 3) & 127;
            int q   = idx & 7;
            const __nv_bfloat16* src;
            if (tl == 0)      src = Ah  + (size_t)(m0 + row) * K + k0 + q * 8;
            else if (tl == 1) src = Al  + (size_t)(m0 + row) * K + k0 + q * 8;
            else if (tl == 2) src = BTh + (size_t)(n0 + row) * K + k0 + q * 8;
            else              src = BTl + (size_t)(n0 + row) * K + k0 + q * 8;
            cp16(stg + tl * 16384 + sw128((uint32_t)(row * 128 + q * 16)), src);
        }
    };

    load_stage(0);
    asm volatile("cp.async.commit_group;" ::: "memory");
    load_stage(1);
    asm volatile("cp.async.commit_group;" ::: "memory");

    const int aRow  = (lane & 15);
    const int aKoff = (lane >> 4) << 4;
    const int bRow  = (lane & 7) + ((lane >> 4) << 3);
    const int bKoff = ((lane >> 3) & 1) << 4;

    for (int s = 0; s < nstage; s++) {
        if (s + 2 < nstage) {
            load_stage(s + 2);
            asm volatile("cp.async.commit_group;" ::: "memory");
            asm volatile("cp.async.wait_group 2;" ::: "memory");
        } else if (s + 1 < nstage) {
            asm volatile("cp.async.wait_group 1;" ::: "memory");
        } else {
            asm volatile("cp.async.wait_group 0;" ::: "memory");
        }
        __syncthreads();

        const uint32_t ab = sb + (uint32_t)(s % 3) * STG_BYTES;

        #pragma unroll
        for (int kk = 0; kk < 4; kk++) {
            const int kb = kk * 32;
            uint32_t a_h[2][4], a_l[2][4];
            #pragma unroll
            for (int im = 0; im < 2; im++) {
                uint32_t off = sw128((uint32_t)((wm * 32 + im * 16 + aRow) * 128 + kb + aKoff));
                ldsm4(a_h[im], ab + off);
                ldsm4(a_l[im], ab + 16384 + off);
            }
            uint32_t b_h[16], b_l[16];
            #pragma unroll
            for (int ib = 0; ib < 4; ib++) {
                uint32_t off = sw128((uint32_t)((wn * 64 + ib * 16 + bRow) * 128 + kb + bKoff));
                ldsm4(&b_h[ib * 4], ab + 32768 + off);
                ldsm4(&b_l[ib * 4], ab + 49152 + off);
            }
            #pragma unroll
            for (int im = 0; im < 2; im++) {
                #pragma unroll
                for (int in = 0; in < 8; in++) {
                    const uint32_t* bh = &b_h[(in >> 1) * 4 + (in & 1) * 2];
                    const uint32_t* bl = &b_l[(in >> 1) * 4 + (in & 1) * 2];
                    mma16816(c[im][in], a_h[im], bh);
                    mma16816(c[im][in], a_l[im], bh);
                    mma16816(c[im][in], a_h[im], bl);
                }
            }
        }
        __syncthreads();
    }
}

// ---------------------------------------------------------------------------
// QKV GEMM: fused projections with RoPE / v-split epilogue.
// N = 3072 columns: [0,2048) Q, [2048,2560) K, [2560,3072) V.
// ---------------------------------------------------------------------------
__global__ void __launch_bounds__(256, 1)
gemm_qkv_kernel(const __nv_bfloat16* __restrict__ Ah, const __nv_bfloat16* __restrict__ Al,
                const __nv_bfloat16* __restrict__ BTh, const __nv_bfloat16* __restrict__ BTl,
                const float* __restrict__ bq, const float* __restrict__ bk,
                const float* __restrict__ bv,
                const float* __restrict__ ct, const float* __restrict__ st,
                __nv_bfloat16* __restrict__ qr, __nv_bfloat16* __restrict__ kr,
                __nv_bfloat16* __restrict__ vh, __nv_bfloat16* __restrict__ vl)
{
    extern __shared__ char dsm[];
    char* smbase = (char*)(((uintptr_t)dsm + 1023) & ~(uintptr_t)1023);
    const uint32_t sb = smem_u32(smbase);
    const int tid  = threadIdx.x;
    const int lane = tid & 31;
    const int wm   = (tid >> 5) >> 1;
    const int wn   = (tid >> 5) & 1;
    const int m0   = blockIdx.y * 128;
    const int n0   = blockIdx.x * 128;

    float c[2][8][4];
    gemm_core(Ah, Al, BTh, BTl, NE, m0, n0, sb, tid, c);

    const int region = (n0 >= NE + KVDIM) ? 2 : (n0 >= NE ? 1 : 0);

    #pragma unroll
    for (int im = 0; im < 2; im++) {
        const int r0 = m0 + wm * 32 + im * 16 + (lane >> 2);
        const int b  = r0 >> 11;
        const int t  = r0 & 2047;
        #pragma unroll
        for (int in = 0; in < 8; in++) {
            const int cc = n0 + wn * 64 + in * 8 + ((lane & 3) << 1);
            float b0, b1;
            if (region == 0)      { b0 = bq[cc];          b1 = bq[cc + 1]; }
            else if (region == 1) { b0 = bk[cc - NE];     b1 = bk[cc - NE + 1]; }
            else                  { b0 = bv[cc - NE - KVDIM]; b1 = bv[cc - NE - KVDIM + 1]; }
            float v0 = c[im][in][0] + b0, v1 = c[im][in][1] + b1;   // row t
            float v2 = c[im][in][2] + b0, v3 = c[im][in][3] + b1;   // row t+8
            const int dloc = cc & 127;
            if (region <= 1) {
                const int i  = dloc >> 1;
                float c0 = ct[t * 64 + i],       s0 = st[t * 64 + i];
                float c2 = ct[(t + 8) * 64 + i], s2 = st[(t + 8) * 64 + i];
                uint32_t p0 = packbf2(__float2bfloat16(v0 * c0 - v1 * s0),
                                      __float2bfloat16(v0 * s0 + v1 * c0));
                uint32_t p2 = packbf2(__float2bfloat16(v2 * c2 - v3 * s2),
                                      __float2bfloat16(v2 * s2 + v3 * c2));
                if (region == 0) {
                    const int h = cc >> 7;
                    size_t dst = ((size_t)((b * NH + h) * TT + t)) * HD + dloc;
                    *(uint32_t*)(qr + dst)          = p0;
                    *(uint32_t*)(qr + dst + 8 * HD) = p2;
                } else {
                    const int h = (cc - NE) >> 7;
                    size_t dst = ((size_t)((b * NKV + h) * TT + t)) * HD + dloc;
                    *(uint32_t*)(kr + dst)          = p0;
                    *(uint32_t*)(kr + dst + 8 * HD) = p2;
                }
            } else {
                const int h = (cc - NE - KVDIM) >> 7;
                size_t dst = ((size_t)((b * NKV + h) * TT + t)) * HD + dloc;
                __nv_bfloat16 h0 = __float2bfloat16(v0);
                __nv_bfloat16 h1 = __float2bfloat16(v1);
                __nv_bfloat16 h2 = __float2bfloat16(v2);
                __nv_bfloat16 h3 = __float2bfloat16(v3);
                *(uint32_t*)(vh + dst) = packbf2(h0, h1);
                *(uint32_t*)(vl + dst) = packbf2(__float2bfloat16(v0 - __bfloat162float(h0)),
                                                 __float2bfloat16(v1 - __bfloat162float(h1)));
                *(uint32_t*)(vh + dst + 8 * HD) = packbf2(h2, h3);
                *(uint32_t*)(vl + dst + 8 * HD) = packbf2(__float2bfloat16(v2 - __bfloat162float(h2)),
                                                          __float2bfloat16(v3 - __bfloat162float(h3)));
            }
        }
    }
}

// ---------------------------------------------------------------------------
// Output projection GEMM: plain bias epilogue -> fp32 out
// ---------------------------------------------------------------------------
__global__ void __launch_bounds__(256, 1)
gemm_out_kernel(const __nv_bfloat16* __restrict__ Ah, const __nv_bfloat16* __restrict__ Al,
                const __nv_bfloat16* __restrict__ BTh, const __nv_bfloat16* __restrict__ BTl,
                const float* __restrict__ bias, float* __restrict__ C)
{
    extern __shared__ char dsm[];
    char* smbase = (char*)(((uintptr_t)dsm + 1023) & ~(uintptr_t)1023);
    const uint32_t sb = smem_u32(smbase);
    const int tid  = threadIdx.x;
    const int lane = tid & 31;
    const int wm   = (tid >> 5) >> 1;
    const int wn   = (tid >> 5) & 1;
    const int m0   = blockIdx.y * 128;
    const int n0   = blockIdx.x * 128;

    float c[2][8][4];
    gemm_core(Ah, Al, BTh, BTl, NE, m0, n0, sb, tid, c);

    #pragma unroll
    for (int im = 0; im < 2; im++) {
        const int r0 = m0 + wm * 32 + im * 16 + (lane >> 2);
        #pragma unroll
        for (int in = 0; in < 8; in++) {
            const int cc = n0 + wn * 64 + in * 8 + ((lane & 3) << 1);
            float2 bb = *(const float2*)&bias[cc];
            float2 o0, o1;
            o0.x = c[im][in][0] + bb.x;  o0.y = c[im][in][1] + bb.y;
            o1.x = c[im][in][2] + bb.x;  o1.y = c[im][in][3] + bb.y;
            *(float2*)&C[(size_t)r0 * NE + cc]       = o0;
            *(float2*)&C[(size_t)(r0 + 8) * NE + cc] = o1;
        }
    }
}

// ---------------------------------------------------------------------------
// Flash attention (causal, GQA) on mma.sync. BM=128, BN=64, 256 threads/8 warps.
// Epilogue writes split-bf16 oh/ol directly (feeds O-projection GEMM).
// smem: Q(128 rows) | {K,Vh,Vl} x 2 buffers (64 rows each), rows 272B.
// ---------------------------------------------------------------------------
#define AT_RS 272
#define AT_T64 (64 * AT_RS)
#define AT_QSZ (128 * AT_RS)
#define ATT_SMEM (AT_QSZ + 6 * AT_T64 + 1024)

__global__ void __launch_bounds__(256, 1)
attn_mma_kernel(const __nv_bfloat16* __restrict__ qr, const __nv_bfloat16* __restrict__ kr,
                const __nv_bfloat16* __restrict__ vh, const __nv_bfloat16* __restrict__ vl,
                __nv_bfloat16* __restrict__ oh, __nv_bfloat16* __restrict__ ol)
{
    extern __shared__ char dsm2[];
    char* smb = (char*)(((uintptr_t)dsm2 + 1023) & ~(uintptr_t)1023);
    const uint32_t sb = smem_u32(smb);

    const int tid  = threadIdx.x;
    const int lane = tid & 31;
    const int w    = tid >> 5;                              // 0..7
    const int mtb  = (int)gridDim.x - 1 - (int)blockIdx.x;  // heavy blocks first
    const int h    = blockIdx.y, b = blockIdx.z;
    const int m0   = mtb * 128;
    const int kv   = h >> 2;
    const int ntile = 2 * mtb + 2;

    const __nv_bfloat16* qg  = qr + ((size_t)(b * NH + h) * TT + m0) * HD;
    const __nv_bfloat16* kg  = kr + ((size_t)(b * NKV + kv) * TT) * HD;
    const __nv_bfloat16* vhg = vh + ((size_t)(b * NKV + kv) * TT) * HD;
    const __nv_bfloat16* vlg = vl + ((size_t)(b * NKV + kv) * TT) * HD;

    const uint32_t Q0 = sb;
    auto toff = [&](int buf, int which) -> uint32_t {
        return sb + AT_QSZ + (uint32_t)AT_T64 * (buf * 3 + which);
    };
    auto load64 = [&](uint32_t dst, const __nv_bfloat16* src) {
        #pragma unroll
        for (int i = 0; i < 4; i++) {
            int idx = tid + i * 256;
            int row = idx >> 4, cq = idx & 15;
            cp16(dst + (uint32_t)(row * AT_RS + cq * 16), src + (size_t)row * HD + cq * 8);
        }
    };

    // Q: 128 rows
    #pragma unroll
    for (int i = 0; i < 8; i++) {
        int idx = tid + i * 256;
        int row = idx >> 4, cq = idx & 15;
        cp16(Q0 + (uint32_t)(row * AT_RS + cq * 16), qg + (size_t)row * HD + cq * 8);
    }
    load64(toff(0, 0), kg);
    load64(toff(0, 1), vhg);
    load64(toff(0, 2), vlg);
    asm volatile("cp.async.commit_group;" ::: "memory");

    uint32_t qf[8][4];
    float ov[16][4];
    #pragma unroll
    for (int n = 0; n < 16; n++) { ov[n][0] = ov[n][1] = ov[n][2] = ov[n][3] = 0.f; }
    float m_lo = -1e30f, m_hi = -1e30f, l_lo = 0.f, l_hi = 0.f;

    const int aRow = lane & 15;
    const int aK   = (lane >> 4) << 4;
    const int bRow = (lane & 7) + ((lane >> 4) << 3);
    const int bK   = ((lane >> 3) & 1) << 4;
    const int vRow = (lane & 7) + (((lane >> 3) & 1) << 3);
    const int vC   = (lane >> 4) << 4;

    for (int jt = 0; jt < ntile; jt++) {
        if (jt + 1 < ntile) {
            int nb = (jt + 1) & 1;
            load64(toff(nb, 0), kg  + (size_t)(jt + 1) * 64 * HD);
            load64(toff(nb, 1), vhg + (size_t)(jt + 1) * 64 * HD);
            load64(toff(nb, 2), vlg + (size_t)(jt + 1) * 64 * HD);
            asm volatile("cp.async.commit_group;" ::: "memory");
            asm volatile("cp.async.wait_group 1;" ::: "memory");
        } else {
            asm volatile("cp.async.wait_group 0;" ::: "memory");
        }
        __syncthreads();

        if (jt == 0) {
            #pragma unroll
            for (int kt = 0; kt < 8; kt++)
                ldsm4(qf[kt], Q0 + (uint32_t)((w * 16 + aRow) * AT_RS + kt * 32 + aK));
        }

        const uint32_t kb  = toff(jt & 1, 0);
        const uint32_t vhb = toff(jt & 1, 1);
        const uint32_t vlb = toff(jt & 1, 2);

        // ---- S = Q @ K^T ----
        float sc[8][4];
        #pragma unroll
        for (int j = 0; j < 8; j++) { sc[j][0] = sc[j][1] = sc[j][2] = sc[j][3] = 0.f; }

        #pragma unroll
        for (int kt = 0; kt < 8; kt++) {
            #pragma unroll
            for (int ib = 0; ib < 4; ib++) {
                uint32_t bf[4];
                ldsm4(bf, kb + (uint32_t)((ib * 16 + bRow) * AT_RS + kt * 32 + bK));
                mma16816(sc[2 * ib],     qf[kt], bf);
                mma16816(sc[2 * ib + 1], qf[kt], bf + 2);
            }
        }

        // ---- causal mask (last two tiles only) ----
        if (jt >= ntile - 2) {
            const int rl = m0 + w * 16 + (lane >> 2);
            #pragma unroll
            for (int j = 0; j < 8; j++) {
                int gn = jt * 64 + j * 8 + ((lane & 3) << 1);
                if (gn     > rl)     sc[j][0] = -1e30f;
                if (gn + 1 > rl)     sc[j][1] = -1e30f;
                if (gn     > rl + 8) sc[j][2] = -1e30f;
                if (gn + 1 > rl + 8) sc[j][3] = -1e30f;
            }
        }

        // ---- online softmax ----
        float vlo = -1e30f, vhi = -1e30f;
        #pragma unroll
        for (int j = 0; j < 8; j++) {
            vlo = fmaxf(vlo, fmaxf(sc[j][0], sc[j][1]));
            vhi = fmaxf(vhi, fmaxf(sc[j][2], sc[j][3]));
        }
        vlo = fmaxf(vlo, __shfl_xor_sync(0xffffffffu, vlo, 1));
        vlo = fmaxf(vlo, __shfl_xor_sync(0xffffffffu, vlo, 2));
        vhi = fmaxf(vhi, __shfl_xor_sync(0xffffffffu, vhi, 1));
        vhi = fmaxf(vhi, __shfl_xor_sync(0xffffffffu, vhi, 2));
        float mn_lo = fmaxf(m_lo, vlo), mn_hi = fmaxf(m_hi, vhi);
        float al_lo = __expf(m_lo - mn_lo), al_hi = __expf(m_hi - mn_hi);
        m_lo = mn_lo; m_hi = mn_hi;
        l_lo *= al_lo; l_hi *= al_hi;
        #pragma unroll
        for (int n = 0; n < 16; n++) {
            ov[n][0] *= al_lo; ov[n][1] *= al_lo;
            ov[n][2] *= al_hi; ov[n][3] *= al_hi;
        }

        uint32_t ph[8][2], pl[8][2];
        #pragma unroll
        for (int j = 0; j < 8; j++) {
            float p0 = __expf(sc[j][0] - m_lo), p1 = __expf(sc[j][1] - m_lo);
            float p2 = __expf(sc[j][2] - m_hi), p3 = __expf(sc[j][3] - m_hi);
            l_lo += p0 + p1;  l_hi += p2 + p3;
            __nv_bfloat16 h0 = __float2bfloat16(p0), h1 = __float2bfloat16(p1);
            __nv_bfloat16 h2 = __float2bfloat16(p2), h3 = __float2bfloat16(p3);
            ph[j][0] = packbf2(h0, h1);
            ph[j][1] = packbf2(h2, h3);
            pl[j][0] = packbf2(__float2bfloat16(p0 - __bfloat162float(h0)),
                               __float2bfloat16(p1 - __bfloat162float(h1)));
            pl[j][1] = packbf2(__float2bfloat16(p2 - __bfloat162float(h2)),
                               __float2bfloat16(p3 - __bfloat162float(h3)));
        }

        // ---- O += P @ V  (3-term split) ----
        #pragma unroll
        for (int kt = 0; kt < 4; kt++) {
            uint32_t ah[4] = { ph[2*kt][0], ph[2*kt][1], ph[2*kt+1][0], ph[2*kt+1][1] };
            uint32_t am[4] = { pl[2*kt][0], pl[2*kt][1], pl[2*kt+1][0], pl[2*kt+1][1] };
            #pragma unroll
            for (int np = 0; np < 4; np++) {
                uint32_t base = (uint32_t)((kt * 16 + vRow) * AT_RS + np * 64 + vC);
                uint32_t bh0[4], bh1[4], bl0[4], bl1[4];
                ldsm4t(bh0, vhb + base);
                ldsm4t(bh1, vhb + base + 32);
                ldsm4t(bl0, vlb + base);
                ldsm4t(bl1, vlb + base + 32);
                mma16816(ov[np*4+0], ah, bh0);
                mma16816(ov[np*4+1], ah, bh0 + 2);
                mma16816(ov[np*4+2], ah, bh1);
                mma16816(ov[np*4+3], ah, bh1 + 2);
                mma16816(ov[np*4+0], am, bh0);
                mma16816(ov[np*4+1], am, bh0 + 2);
                mma16816(ov[np*4+2], am, bh1);
                mma16816(ov[np*4+3], am, bh1 + 2);
                mma16816(ov[np*4+0], ah, bl0);
                mma16816(ov[np*4+1], ah, bl0 + 2);
                mma16816(ov[np*4+2], ah, bl1);
                mma16816(ov[np*4+3], ah, bl1 + 2);
            }
        }
        __syncthreads();
    }

    // ---- epilogue: normalize, split-bf16, write oh/ol ----
    l_lo += __shfl_xor_sync(0xffffffffu, l_lo, 1);
    l_lo += __shfl_xor_sync(0xffffffffu, l_lo, 2);
    l_hi += __shfl_xor_sync(0xffffffffu, l_hi, 1);
    l_hi += __shfl_xor_sync(0xffffffffu, l_hi, 2);
    const float inv_lo = 0.022097086912079608f / l_lo;
    const float inv_hi = 0.022097086912079608f / l_hi;
    const int rlo = m0 + w * 16 + (lane >> 2);
    size_t base = ((size_t)(b * TT) + rlo) * NE + h * HD;
    #pragma unroll
    for (int n = 0; n < 16; n++) {
        int d = n * 8 + ((lane & 3) << 1);
        float o0 = ov[n][0] * inv_lo, o1 = ov[n][1] * inv_lo;
        float o2 = ov[n][2] * inv_hi, o3 = ov[n][3] * inv_hi;
        __nv_bfloat16 h0 = __float2bfloat16(o0), h1 = __float2bfloat16(o1);
        __nv_bfloat16 h2 = __float2bfloat16(o2), h3 = __float2bfloat16(o3);
        *(uint32_t*)(oh + base + d) = packbf2(h0, h1);
        *(uint32_t*)(ol + base + d) = packbf2(__float2bfloat16(o0 - __bfloat162float(h0)),
                                              __float2bfloat16(o1 - __bfloat162float(h1)));
        *(uint32_t*)(oh + base + 8 * NE + d) = packbf2(h2, h3);
        *(uint32_t*)(ol + base + 8 * NE + d) = packbf2(__float2bfloat16(o2 - __bfloat162float(h2)),
                                                       __float2bfloat16(o3 - __bfloat162float(h3)));
    }
}

// ---------------------------------------------------------------------------
// launch
// ---------------------------------------------------------------------------
extern "C" void kernel_launch(void* const* d_in, const int* in_sizes, int n_in,
                              void* d_out, int out_size)
{
    const float* x  = (const float*)d_in[0];
    const float* Wq = (const float*)d_in[1];
    const float* bq = (const float*)d_in[2];
    const float* Wk = (const float*)d_in[3];
    const float* bk = (const float*)d_in[4];
    const float* Wv = (const float*)d_in[5];
    const float* bv = (const float*)d_in[6];
    const float* Wo = (const float*)d_in[7];
    const float* bo = (const float*)d_in[8];
    float* out = (float*)d_out;

    float *ct, *st;
    __nv_bfloat16 *qr, *kr, *vhp, *vlp;
    __nv_bfloat16 *xh, *xl, *oh, *ol;
    __nv_bfloat16 *wqkvh, *wqkvl, *woh, *wol;
    cudaGetSymbolAddress((void**)&ct, g_cos);
    cudaGetSymbolAddress((void**)&st, g_sin);
    cudaGetSymbolAddress((void**)&qr, g_qr);
    cudaGetSymbolAddress((void**)&kr, g_kr);
    cudaGetSymbolAddress((void**)&vhp, g_vh);
    cudaGetSymbolAddress((void**)&vlp, g_vl);
    cudaGetSymbolAddress((void**)&xh, g_xh);
    cudaGetSymbolAddress((void**)&xl, g_xl);
    cudaGetSymbolAddress((void**)&oh, g_oh);
    cudaGetSymbolAddress((void**)&ol, g_ol);
    cudaGetSymbolAddress((void**)&wqkvh, g_wqkvh);
    cudaGetSymbolAddress((void**)&wqkvl, g_wqkvl);
    cudaGetSymbolAddress((void**)&woh, g_woh);
    cudaGetSymbolAddress((void**)&wol, g_wol);

    cudaFuncSetAttribute(gemm_qkv_kernel, cudaFuncAttributeMaxDynamicSharedMemorySize, GEMM_SMEM);
    cudaFuncSetAttribute(gemm_out_kernel, cudaFuncAttributeMaxDynamicSharedMemorySize, GEMM_SMEM);
    cudaFuncSetAttribute(attn_mma_kernel, cudaFuncAttributeMaxDynamicSharedMemorySize, ATT_SMEM);

    // prep: weight transposes into packed buffer + x split + rope table
    tsplit_kernel<<<dim3(NE / 32, NE / 32), 256>>>(Wq, wqkvh, wqkvl, NE, NE);
    tsplit_kernel<<<dim3(KVDIM / 32, NE / 32), 256>>>(Wk, wqkvh + (size_t)NE * NE,
                                                      wqkvl + (size_t)NE * NE, NE, KVDIM);
    tsplit_kernel<<<dim3(KVDIM / 32, NE / 32), 256>>>(Wv, wqkvh + (size_t)(NE + KVDIM) * NE,
                                                      wqkvl + (size_t)(NE + KVDIM) * NE, NE, KVDIM);
    tsplit_kernel<<<dim3(NE / 32, NE / 32), 256>>>(Wo, woh, wol, NE, NE);
    split_kernel<<<(MROWS * NE / 8 + 255) / 256, 256>>>(x, xh, xl, MROWS * NE / 8);
    rope_table_kernel<<<(TT * 64 + 255) / 256, 256>>>(ct, st);

    // fused QKV projection (rope + v-split epilogue)
    gemm_qkv_kernel<<<dim3(NQKV / 128, MROWS / 128), 256, GEMM_SMEM>>>(
        xh, xl, wqkvh, wqkvl, bq, bk, bv, ct, st, qr, kr, vhp, vlp);

    // attention (writes split-bf16 oh/ol)
    {
        dim3 grid(TT / 128, NH, BB);
        attn_mma_kernel<<<grid, 256, ATT_SMEM>>>(qr, kr, vhp, vlp, oh, ol);
    }

    // output projection
    gemm_out_kernel<<<dim3(NE / 128, MROWS / 128), 256, GEMM_SMEM>>>(
        oh, ol, woh, wol, bo, out);
}

// round 8
// speedup vs baseline: 4.0903x; 1.0204x over previous
#include <cuda_runtime.h>
#include <cuda_bf16.h>
#include <cstdint>
#include <cmath>

// ---------------------------------------------------------------------------
// Problem constants (fixed shapes)
// ---------------------------------------------------------------------------
#define BB 2
#define TT 2048
#define NE 2048          // N_EMBED
#define NH 16            // N_HEAD
#define NKV 4            // N_KV_HEAD
#define HD 128           // HEAD_DIM
#define MROWS (BB*TT)    // 4096
#define KVDIM (NKV*HD)   // 512
#define NQKV (NE + 2*KVDIM)   // 3072

// ---------------------------------------------------------------------------
// Scratch (static device globals; no allocations allowed)
// ---------------------------------------------------------------------------
__device__ __nv_bfloat16 g_qr[(size_t)BB * NH * TT * HD];   // rope(q) bf16 [B,H,T,D]
__device__ __nv_bfloat16 g_kr[(size_t)BB * NKV * TT * HD];  // rope(k) bf16 [B,KV,T,D]
__device__ __nv_bfloat16 g_vh[(size_t)BB * NKV * TT * HD];  // v hi bf16 [B,KV,T,D]
__device__ __nv_bfloat16 g_vl[(size_t)BB * NKV * TT * HD];  // v lo bf16 [B,KV,T,D]
__device__ float g_cos[TT * (HD/2)];
__device__ float g_sin[TT * (HD/2)];

// split-bf16 operands for tensor-core GEMMs
__device__ __nv_bfloat16 g_xh[(size_t)MROWS * NE];
__device__ __nv_bfloat16 g_xl[(size_t)MROWS * NE];
__device__ __nv_bfloat16 g_oh[(size_t)MROWS * NE];   // attn out hi
__device__ __nv_bfloat16 g_ol[(size_t)MROWS * NE];   // attn out lo
// packed transposed weights [N][K] hi/lo: rows 0..2047 Wq^T, 2048..2559 Wk^T, 2560..3071 Wv^T
__device__ __nv_bfloat16 g_wqkvh[(size_t)NQKV * NE];
__device__ __nv_bfloat16 g_wqkvl[(size_t)NQKV * NE];
__device__ __nv_bfloat16 g_woh[(size_t)NE * NE];
__device__ __nv_bfloat16 g_wol[(size_t)NE * NE];

// ---------------------------------------------------------------------------
// Helpers (baseline PTX only — no sm_103a-suffixed features)
// ---------------------------------------------------------------------------
__device__ __forceinline__ uint32_t smem_u32(const void* p) {
    uint32_t a;
    asm("{ .reg .u64 t; cvta.to.shared.u64 t, %1; cvt.u32.u64 %0, t; }" : "=r"(a) : "l"(p));
    return a;
}
__device__ __forceinline__ uint32_t sw128(uint32_t off) {
    return off ^ ((off >> 3) & 0x70);
}
__device__ __forceinline__ void cp16(uint32_t dst, const void* src) {
    asm volatile("cp.async.cg.shared.global [%0], [%1], 16;" :: "r"(dst), "l"(src) : "memory");
}
__device__ __forceinline__ void ldsm4(uint32_t* r, uint32_t addr) {
    asm volatile("ldmatrix.sync.aligned.m8n8.x4.shared.b16 {%0,%1,%2,%3}, [%4];"
                 : "=r"(r[0]), "=r"(r[1]), "=r"(r[2]), "=r"(r[3]) : "r"(addr));
}
__device__ __forceinline__ void ldsm4t(uint32_t* r, uint32_t addr) {
    asm volatile("ldmatrix.sync.aligned.m8n8.x4.trans.shared.b16 {%0,%1,%2,%3}, [%4];"
                 : "=r"(r[0]), "=r"(r[1]), "=r"(r[2]), "=r"(r[3]) : "r"(addr));
}
__device__ __forceinline__ void mma16816(float* c, const uint32_t* a, const uint32_t* b) {
    asm volatile(
        "mma.sync.aligned.m16n8k16.row.col.f32.bf16.bf16.f32 "
        "{%0,%1,%2,%3}, {%4,%5,%6,%7}, {%8,%9}, {%0,%1,%2,%3};"
        : "+f"(c[0]), "+f"(c[1]), "+f"(c[2]), "+f"(c[3])
        : "r"(a[0]), "r"(a[1]), "r"(a[2]), "r"(a[3]), "r"(b[0]), "r"(b[1]));
}
__device__ __forceinline__ uint32_t packbf2(__nv_bfloat16 lo, __nv_bfloat16 hi) {
    return ((uint32_t)__bfloat16_as_ushort(hi) << 16) | (uint32_t)__bfloat16_as_ushort(lo);
}

// ---------------------------------------------------------------------------
// Prep kernels
// ---------------------------------------------------------------------------
__global__ void __launch_bounds__(256)
split_kernel(const float* __restrict__ x, __nv_bfloat16* __restrict__ xh,
             __nv_bfloat16* __restrict__ xl, int n8)
{
    int i = blockIdx.x * 256 + threadIdx.x;
    if (i >= n8) return;
    size_t base = (size_t)i * 8;
    float4 v0 = *(const float4*)(x + base);
    float4 v1 = *(const float4*)(x + base + 4);
    float vv[8] = {v0.x, v0.y, v0.z, v0.w, v1.x, v1.y, v1.z, v1.w};
    union { __nv_bfloat16 b[8]; uint4 u; } ph, pl;
    #pragma unroll
    for (int j = 0; j < 8; j++) {
        __nv_bfloat16 h = __float2bfloat16(vv[j]);
        ph.b[j] = h;
        pl.b[j] = __float2bfloat16(vv[j] - __bfloat162float(h));
    }
    *(uint4*)(xh + base) = ph.u;
    *(uint4*)(xl + base) = pl.u;
}

// W[K][N] row-major -> Th/Tl[N][K] bf16
__global__ void __launch_bounds__(256)
tsplit_kernel(const float* __restrict__ W, __nv_bfloat16* __restrict__ Th,
              __nv_bfloat16* __restrict__ Tl, int K, int N)
{
    __shared__ float t[32][33];
    int n0 = blockIdx.x * 32, k0 = blockIdx.y * 32;
    int tx = threadIdx.x & 31, ty = threadIdx.x >> 5;   // 32x8
    #pragma unroll
    for (int i = 0; i < 4; i++)
        t[ty + i * 8][tx] = W[(size_t)(k0 + ty + i * 8) * N + n0 + tx];
    __syncthreads();
    #pragma unroll
    for (int i = 0; i < 4; i++) {
        int n = n0 + ty + i * 8, k = k0 + tx;
        float v = t[tx][ty + i * 8];
        __nv_bfloat16 h = __float2bfloat16(v);
        Th[(size_t)n * K + k] = h;
        Tl[(size_t)n * K + k] = __float2bfloat16(v - __bfloat162float(h));
    }
}

// RoPE table: angle = fp32(t) * fp32(double-precision freq)
__global__ void __launch_bounds__(256)
rope_table_kernel(float* __restrict__ ct, float* __restrict__ st)
{
    int idx = blockIdx.x * 256 + threadIdx.x;
    if (idx >= TT * (HD/2)) return;
    int t = idx >> 6;
    int i = idx & 63;
    double fr = exp(-((double)(2 * i) / (double)NE) * log(10000.0));
    float ff = (float)fr;
    float ang = __fmul_rn((float)t, ff);
    float s, c;
    sincosf(ang, &s, &c);
    ct[idx] = c;
    st[idx] = s;
}

// ---------------------------------------------------------------------------
// GEMM core: split-bf16 C = Ah@Bh^T + Ah@Bl^T + Al@Bh^T
// BM=256, BN=128, BK=64, 256 threads (4m x 2n warps, warp tile 64x64),
// 2-stage cp.async pipeline.
// Stage layout: Ah@0(32K) | Al@32K | Bh@64K(16K) | Bl@80K  (rows 128B, SW128)
// ---------------------------------------------------------------------------
#define STG_BYTES 98304
#define GEMM_SMEM (2*STG_BYTES + 1024)

__device__ __forceinline__ void gemm_core(
    const __nv_bfloat16* __restrict__ Ah, const __nv_bfloat16* __restrict__ Al,
    const __nv_bfloat16* __restrict__ BTh, const __nv_bfloat16* __restrict__ BTl,
    int K, int m0, int n0, uint32_t sb, int tid, float c[4][8][4])
{
    const int lane = tid & 31;
    const int wm   = (tid >> 5) >> 1;   // 0..3 (64 rows each)
    const int wn   = (tid >> 5) & 1;    // 0..1 (64 cols each)
    const int nstage = K / 64;

    #pragma unroll
    for (int im = 0; im < 4; im++)
        #pragma unroll
        for (int in = 0; in < 8; in++)
            #pragma unroll
            for (int j = 0; j < 4; j++) c[im][in][j] = 0.f;

    auto load_stage = [&](int s) {
        const int k0 = s * 64;
        const uint32_t stg = sb + (uint32_t)(s & 1) * STG_BYTES;
        // A: 2 mats x 256 rows x 8 quads = 4096 ; B: 2 x 128 x 8 = 2048
        #pragma unroll
        for (int i = 0; i < 24; i++) {
            int idx = tid + (i << 8);           // 0..6143
            if (idx < 4096) {
                int mat = idx >> 11;
                int row = (idx >> 3) & 255;
                int q   = idx & 7;
                const __nv_bfloat16* src =
                    (mat ? Al : Ah) + (size_t)(m0 + row) * K + k0 + q * 8;
                cp16(stg + mat * 32768 + sw128((uint32_t)(row * 128 + q * 16)), src);
            } else {
                int rel = idx - 4096;
                int mat = rel >> 10;
                int row = (rel >> 3) & 127;
                int q   = rel & 7;
                const __nv_bfloat16* src =
                    (mat ? BTl : BTh) + (size_t)(n0 + row) * K + k0 + q * 8;
                cp16(stg + 65536 + mat * 16384 + sw128((uint32_t)(row * 128 + q * 16)), src);
            }
        }
    };

    load_stage(0);
    asm volatile("cp.async.commit_group;" ::: "memory");

    const int aRow  = (lane & 15);
    const int aKoff = (lane >> 4) << 4;
    const int bRow  = (lane & 7) + ((lane >> 4) << 3);
    const int bKoff = ((lane >> 3) & 1) << 4;

    for (int s = 0; s < nstage; s++) {
        if (s + 1 < nstage) {
            load_stage(s + 1);
            asm volatile("cp.async.commit_group;" ::: "memory");
            asm volatile("cp.async.wait_group 1;" ::: "memory");
        } else {
            asm volatile("cp.async.wait_group 0;" ::: "memory");
        }
        __syncthreads();

        const uint32_t ab = sb + (uint32_t)(s & 1) * STG_BYTES;

        #pragma unroll
        for (int kk = 0; kk < 4; kk++) {
            const int kb = kk * 32;
            uint32_t a_h[4][4], a_l[4][4];
            #pragma unroll
            for (int im = 0; im < 4; im++) {
                uint32_t off = sw128((uint32_t)((wm * 64 + im * 16 + aRow) * 128 + kb + aKoff));
                ldsm4(a_h[im], ab + off);
                ldsm4(a_l[im], ab + 32768 + off);
            }
            uint32_t b_h[16], b_l[16];
            #pragma unroll
            for (int ib = 0; ib < 4; ib++) {
                uint32_t off = sw128((uint32_t)((wn * 64 + ib * 16 + bRow) * 128 + kb + bKoff));
                ldsm4(&b_h[ib * 4], ab + 65536 + off);
                ldsm4(&b_l[ib * 4], ab + 81920 + off);
            }
            #pragma unroll
            for (int im = 0; im < 4; im++) {
                #pragma unroll
                for (int in = 0; in < 8; in++) {
                    const uint32_t* bh = &b_h[(in >> 1) * 4 + (in & 1) * 2];
                    const uint32_t* bl = &b_l[(in >> 1) * 4 + (in & 1) * 2];
                    mma16816(c[im][in], a_h[im], bh);
                    mma16816(c[im][in], a_l[im], bh);
                    mma16816(c[im][in], a_h[im], bl);
                }
            }
        }
        __syncthreads();
    }
}

// ---------------------------------------------------------------------------
// QKV GEMM: fused projections with RoPE / v-split epilogue.
// N = 3072 columns: [0,2048) Q, [2048,2560) K, [2560,3072) V.
// ---------------------------------------------------------------------------
__global__ void __launch_bounds__(256, 1)
gemm_qkv_kernel(const __nv_bfloat16* __restrict__ Ah, const __nv_bfloat16* __restrict__ Al,
                const __nv_bfloat16* __restrict__ BTh, const __nv_bfloat16* __restrict__ BTl,
                const float* __restrict__ bq, const float* __restrict__ bk,
                const float* __restrict__ bv,
                const float* __restrict__ ct, const float* __restrict__ st,
                __nv_bfloat16* __restrict__ qr, __nv_bfloat16* __restrict__ kr,
                __nv_bfloat16* __restrict__ vh, __nv_bfloat16* __restrict__ vl)
{
    extern __shared__ char dsm[];
    char* smbase = (char*)(((uintptr_t)dsm + 1023) & ~(uintptr_t)1023);
    const uint32_t sb = smem_u32(smbase);
    const int tid  = threadIdx.x;
    const int lane = tid & 31;
    const int wm   = (tid >> 5) >> 1;
    const int wn   = (tid >> 5) & 1;
    const int m0   = blockIdx.y * 256;
    const int n0   = blockIdx.x * 128;

    float c[4][8][4];
    gemm_core(Ah, Al, BTh, BTl, NE, m0, n0, sb, tid, c);

    const int region = (n0 >= NE + KVDIM) ? 2 : (n0 >= NE ? 1 : 0);

    #pragma unroll
    for (int im = 0; im < 4; im++) {
        const int r0 = m0 + wm * 64 + im * 16 + (lane >> 2);
        const int b  = r0 >> 11;
        const int t  = r0 & 2047;
        #pragma unroll
        for (int in = 0; in < 8; in++) {
            const int cc = n0 + wn * 64 + in * 8 + ((lane & 3) << 1);
            float b0, b1;
            if (region == 0)      { b0 = bq[cc];          b1 = bq[cc + 1]; }
            else if (region == 1) { b0 = bk[cc - NE];     b1 = bk[cc - NE + 1]; }
            else                  { b0 = bv[cc - NE - KVDIM]; b1 = bv[cc - NE - KVDIM + 1]; }
            float v0 = c[im][in][0] + b0, v1 = c[im][in][1] + b1;   // row t
            float v2 = c[im][in][2] + b0, v3 = c[im][in][3] + b1;   // row t+8
            const int dloc = cc & 127;
            if (region <= 1) {
                const int i  = dloc >> 1;
                float c0 = ct[t * 64 + i],       s0 = st[t * 64 + i];
                float c2 = ct[(t + 8) * 64 + i], s2 = st[(t + 8) * 64 + i];
                uint32_t p0 = packbf2(__float2bfloat16(v0 * c0 - v1 * s0),
                                      __float2bfloat16(v0 * s0 + v1 * c0));
                uint32_t p2 = packbf2(__float2bfloat16(v2 * c2 - v3 * s2),
                                      __float2bfloat16(v2 * s2 + v3 * c2));
                if (region == 0) {
                    const int h = cc >> 7;
                    size_t dst = ((size_t)((b * NH + h) * TT + t)) * HD + dloc;
                    *(uint32_t*)(qr + dst)          = p0;
                    *(uint32_t*)(qr + dst + 8 * HD) = p2;
                } else {
                    const int h = (cc - NE) >> 7;
                    size_t dst = ((size_t)((b * NKV + h) * TT + t)) * HD + dloc;
                    *(uint32_t*)(kr + dst)          = p0;
                    *(uint32_t*)(kr + dst + 8 * HD) = p2;
                }
            } else {
                const int h = (cc - NE - KVDIM) >> 7;
                size_t dst = ((size_t)((b * NKV + h) * TT + t)) * HD + dloc;
                __nv_bfloat16 h0 = __float2bfloat16(v0);
                __nv_bfloat16 h1 = __float2bfloat16(v1);
                __nv_bfloat16 h2 = __float2bfloat16(v2);
                __nv_bfloat16 h3 = __float2bfloat16(v3);
                *(uint32_t*)(vh + dst) = packbf2(h0, h1);
                *(uint32_t*)(vl + dst) = packbf2(__float2bfloat16(v0 - __bfloat162float(h0)),
                                                 __float2bfloat16(v1 - __bfloat162float(h1)));
                *(uint32_t*)(vh + dst + 8 * HD) = packbf2(h2, h3);
                *(uint32_t*)(vl + dst + 8 * HD) = packbf2(__float2bfloat16(v2 - __bfloat162float(h2)),
                                                          __float2bfloat16(v3 - __bfloat162float(h3)));
            }
        }
    }
}

// ---------------------------------------------------------------------------
// Output projection GEMM: plain bias epilogue -> fp32 out
// ---------------------------------------------------------------------------
__global__ void __launch_bounds__(256, 1)
gemm_out_kernel(const __nv_bfloat16* __restrict__ Ah, const __nv_bfloat16* __restrict__ Al,
                const __nv_bfloat16* __restrict__ BTh, const __nv_bfloat16* __restrict__ BTl,
                const float* __restrict__ bias, float* __restrict__ C)
{
    extern __shared__ char dsm[];
    char* smbase = (char*)(((uintptr_t)dsm + 1023) & ~(uintptr_t)1023);
    const uint32_t sb = smem_u32(smbase);
    const int tid  = threadIdx.x;
    const int lane = tid & 31;
    const int wm   = (tid >> 5) >> 1;
    const int wn   = (tid >> 5) & 1;
    const int m0   = blockIdx.y * 256;
    const int n0   = blockIdx.x * 128;

    float c[4][8][4];
    gemm_core(Ah, Al, BTh, BTl, NE, m0, n0, sb, tid, c);

    #pragma unroll
    for (int im = 0; im < 4; im++) {
        const int r0 = m0 + wm * 64 + im * 16 + (lane >> 2);
        #pragma unroll
        for (int in = 0; in < 8; in++) {
            const int cc = n0 + wn * 64 + in * 8 + ((lane & 3) << 1);
            float2 bb = *(const float2*)&bias[cc];
            float2 o0, o1;
            o0.x = c[im][in][0] + bb.x;  o0.y = c[im][in][1] + bb.y;
            o1.x = c[im][in][2] + bb.x;  o1.y = c[im][in][3] + bb.y;
            *(float2*)&C[(size_t)r0 * NE + cc]       = o0;
            *(float2*)&C[(size_t)(r0 + 8) * NE + cc] = o1;
        }
    }
}

// ---------------------------------------------------------------------------
// Flash attention (causal, GQA) on mma.sync. BM=128, BN=64, 256 threads/8 warps.
// Epilogue writes split-bf16 oh/ol directly (feeds O-projection GEMM).
// smem: Q(128 rows) | {K,Vh,Vl} x 2 buffers (64 rows each), rows 272B.
// ---------------------------------------------------------------------------
#define AT_RS 272
#define AT_T64 (64 * AT_RS)
#define AT_QSZ (128 * AT_RS)
#define ATT_SMEM (AT_QSZ + 6 * AT_T64 + 1024)

__global__ void __launch_bounds__(256, 1)
attn_mma_kernel(const __nv_bfloat16* __restrict__ qr, const __nv_bfloat16* __restrict__ kr,
                const __nv_bfloat16* __restrict__ vh, const __nv_bfloat16* __restrict__ vl,
                __nv_bfloat16* __restrict__ oh, __nv_bfloat16* __restrict__ ol)
{
    extern __shared__ char dsm2[];
    char* smb = (char*)(((uintptr_t)dsm2 + 1023) & ~(uintptr_t)1023);
    const uint32_t sb = smem_u32(smb);

    const int tid  = threadIdx.x;
    const int lane = tid & 31;
    const int w    = tid >> 5;                              // 0..7
    const int mtb  = (int)gridDim.x - 1 - (int)blockIdx.x;  // heavy blocks first
    const int h    = blockIdx.y, b = blockIdx.z;
    const int m0   = mtb * 128;
    const int kv   = h >> 2;
    const int ntile = 2 * mtb + 2;

    const __nv_bfloat16* qg  = qr + ((size_t)(b * NH + h) * TT + m0) * HD;
    const __nv_bfloat16* kg  = kr + ((size_t)(b * NKV + kv) * TT) * HD;
    const __nv_bfloat16* vhg = vh + ((size_t)(b * NKV + kv) * TT) * HD;
    const __nv_bfloat16* vlg = vl + ((size_t)(b * NKV + kv) * TT) * HD;

    const uint32_t Q0 = sb;
    auto toff = [&](int buf, int which) -> uint32_t {
        return sb + AT_QSZ + (uint32_t)AT_T64 * (buf * 3 + which);
    };
    auto load64 = [&](uint32_t dst, const __nv_bfloat16* src) {
        #pragma unroll
        for (int i = 0; i < 4; i++) {
            int idx = tid + i * 256;
            int row = idx >> 4, cq = idx & 15;
            cp16(dst + (uint32_t)(row * AT_RS + cq * 16), src + (size_t)row * HD + cq * 8);
        }
    };

    // Q: 128 rows
    #pragma unroll
    for (int i = 0; i < 8; i++) {
        int idx = tid + i * 256;
        int row = idx >> 4, cq = idx & 15;
        cp16(Q0 + (uint32_t)(row * AT_RS + cq * 16), qg + (size_t)row * HD + cq * 8);
    }
    load64(toff(0, 0), kg);
    load64(toff(0, 1), vhg);
    load64(toff(0, 2), vlg);
    asm volatile("cp.async.commit_group;" ::: "memory");

    uint32_t qf[8][4];
    float ov[16][4];
    #pragma unroll
    for (int n = 0; n < 16; n++) { ov[n][0] = ov[n][1] = ov[n][2] = ov[n][3] = 0.f; }
    float m_lo = -1e30f, m_hi = -1e30f, l_lo = 0.f, l_hi = 0.f;

    const int aRow = lane & 15;
    const int aK   = (lane >> 4) << 4;
    const int bRow = (lane & 7) + ((lane >> 4) << 3);
    const int bK   = ((lane >> 3) & 1) << 4;
    const int vRow = (lane & 7) + (((lane >> 3) & 1) << 3);
    const int vC   = (lane >> 4) << 4;

    for (int jt = 0; jt < ntile; jt++) {
        if (jt + 1 < ntile) {
            int nb = (jt + 1) & 1;
            load64(toff(nb, 0), kg  + (size_t)(jt + 1) * 64 * HD);
            load64(toff(nb, 1), vhg + (size_t)(jt + 1) * 64 * HD);
            load64(toff(nb, 2), vlg + (size_t)(jt + 1) * 64 * HD);
            asm volatile("cp.async.commit_group;" ::: "memory");
            asm volatile("cp.async.wait_group 1;" ::: "memory");
        } else {
            asm volatile("cp.async.wait_group 0;" ::: "memory");
        }
        __syncthreads();

        if (jt == 0) {
            #pragma unroll
            for (int kt = 0; kt < 8; kt++)
                ldsm4(qf[kt], Q0 + (uint32_t)((w * 16 + aRow) * AT_RS + kt * 32 + aK));
        }

        const uint32_t kb  = toff(jt & 1, 0);
        const uint32_t vhb = toff(jt & 1, 1);
        const uint32_t vlb = toff(jt & 1, 2);

        // ---- S = Q @ K^T ----
        float sc[8][4];
        #pragma unroll
        for (int j = 0; j < 8; j++) { sc[j][0] = sc[j][1] = sc[j][2] = sc[j][3] = 0.f; }

        #pragma unroll
        for (int kt = 0; kt < 8; kt++) {
            #pragma unroll
            for (int ib = 0; ib < 4; ib++) {
                uint32_t bf[4];
                ldsm4(bf, kb + (uint32_t)((ib * 16 + bRow) * AT_RS + kt * 32 + bK));
                mma16816(sc[2 * ib],     qf[kt], bf);
                mma16816(sc[2 * ib + 1], qf[kt], bf + 2);
            }
        }

        // ---- causal mask (last two tiles only) ----
        if (jt >= ntile - 2) {
            const int rl = m0 + w * 16 + (lane >> 2);
            #pragma unroll
            for (int j = 0; j < 8; j++) {
                int gn = jt * 64 + j * 8 + ((lane & 3) << 1);
                if (gn     > rl)     sc[j][0] = -1e30f;
                if (gn + 1 > rl)     sc[j][1] = -1e30f;
                if (gn     > rl + 8) sc[j][2] = -1e30f;
                if (gn + 1 > rl + 8) sc[j][3] = -1e30f;
            }
        }

        // ---- online softmax ----
        float vlo = -1e30f, vhi = -1e30f;
        #pragma unroll
        for (int j = 0; j < 8; j++) {
            vlo = fmaxf(vlo, fmaxf(sc[j][0], sc[j][1]));
            vhi = fmaxf(vhi, fmaxf(sc[j][2], sc[j][3]));
        }
        vlo = fmaxf(vlo, __shfl_xor_sync(0xffffffffu, vlo, 1));
        vlo = fmaxf(vlo, __shfl_xor_sync(0xffffffffu, vlo, 2));
        vhi = fmaxf(vhi, __shfl_xor_sync(0xffffffffu, vhi, 1));
        vhi = fmaxf(vhi, __shfl_xor_sync(0xffffffffu, vhi, 2));
        float mn_lo = fmaxf(m_lo, vlo), mn_hi = fmaxf(m_hi, vhi);
        float al_lo = __expf(m_lo - mn_lo), al_hi = __expf(m_hi - mn_hi);
        m_lo = mn_lo; m_hi = mn_hi;
        l_lo *= al_lo; l_hi *= al_hi;
        #pragma unroll
        for (int n = 0; n < 16; n++) {
            ov[n][0] *= al_lo; ov[n][1] *= al_lo;
            ov[n][2] *= al_hi; ov[n][3] *= al_hi;
        }

        uint32_t ph[8][2], pl[8][2];
        #pragma unroll
        for (int j = 0; j < 8; j++) {
            float p0 = __expf(sc[j][0] - m_lo), p1 = __expf(sc[j][1] - m_lo);
            float p2 = __expf(sc[j][2] - m_hi), p3 = __expf(sc[j][3] - m_hi);
            l_lo += p0 + p1;  l_hi += p2 + p3;
            __nv_bfloat16 h0 = __float2bfloat16(p0), h1 = __float2bfloat16(p1);
            __nv_bfloat16 h2 = __float2bfloat16(p2), h3 = __float2bfloat16(p3);
            ph[j][0] = packbf2(h0, h1);
            ph[j][1] = packbf2(h2, h3);
            pl[j][0] = packbf2(__float2bfloat16(p0 - __bfloat162float(h0)),
                               __float2bfloat16(p1 - __bfloat162float(h1)));
            pl[j][1] = packbf2(__float2bfloat16(p2 - __bfloat162float(h2)),
                               __float2bfloat16(p3 - __bfloat162float(h3)));
        }

        // ---- O += P @ V  (3-term split) ----
        #pragma unroll
        for (int kt = 0; kt < 4; kt++) {
            uint32_t ah[4] = { ph[2*kt][0], ph[2*kt][1], ph[2*kt+1][0], ph[2*kt+1][1] };
            uint32_t am[4] = { pl[2*kt][0], pl[2*kt][1], pl[2*kt+1][0], pl[2*kt+1][1] };
            #pragma unroll
            for (int np = 0; np < 4; np++) {
                uint32_t base = (uint32_t)((kt * 16 + vRow) * AT_RS + np * 64 + vC);
                uint32_t bh0[4], bh1[4], bl0[4], bl1[4];
                ldsm4t(bh0, vhb + base);
                ldsm4t(bh1, vhb + base + 32);
                ldsm4t(bl0, vlb + base);
                ldsm4t(bl1, vlb + base + 32);
                mma16816(ov[np*4+0], ah, bh0);
                mma16816(ov[np*4+1], ah, bh0 + 2);
                mma16816(ov[np*4+2], ah, bh1);
                mma16816(ov[np*4+3], ah, bh1 + 2);
                mma16816(ov[np*4+0], am, bh0);
                mma16816(ov[np*4+1], am, bh0 + 2);
                mma16816(ov[np*4+2], am, bh1);
                mma16816(ov[np*4+3], am, bh1 + 2);
                mma16816(ov[np*4+0], ah, bl0);
                mma16816(ov[np*4+1], ah, bl0 + 2);
                mma16816(ov[np*4+2], ah, bl1);
                mma16816(ov[np*4+3], ah, bl1 + 2);
            }
        }
        __syncthreads();
    }

    // ---- epilogue: normalize, split-bf16, write oh/ol ----
    l_lo += __shfl_xor_sync(0xffffffffu, l_lo, 1);
    l_lo += __shfl_xor_sync(0xffffffffu, l_lo, 2);
    l_hi += __shfl_xor_sync(0xffffffffu, l_hi, 1);
    l_hi += __shfl_xor_sync(0xffffffffu, l_hi, 2);
    const float inv_lo = 0.022097086912079608f / l_lo;
    const float inv_hi = 0.022097086912079608f / l_hi;
    const int rlo = m0 + w * 16 + (lane >> 2);
    size_t base = ((size_t)(b * TT) + rlo) * NE + h * HD;
    #pragma unroll
    for (int n = 0; n < 16; n++) {
        int d = n * 8 + ((lane & 3) << 1);
        float o0 = ov[n][0] * inv_lo, o1 = ov[n][1] * inv_lo;
        float o2 = ov[n][2] * inv_hi, o3 = ov[n][3] * inv_hi;
        __nv_bfloat16 h0 = __float2bfloat16(o0), h1 = __float2bfloat16(o1);
        __nv_bfloat16 h2 = __float2bfloat16(o2), h3 = __float2bfloat16(o3);
        *(uint32_t*)(oh + base + d) = packbf2(h0, h1);
        *(uint32_t*)(ol + base + d) = packbf2(__float2bfloat16(o0 - __bfloat162float(h0)),
                                              __float2bfloat16(o1 - __bfloat162float(h1)));
        *(uint32_t*)(oh + base + 8 * NE + d) = packbf2(h2, h3);
        *(uint32_t*)(ol + base + 8 * NE + d) = packbf2(__float2bfloat16(o2 - __bfloat162float(h2)),
                                                       __float2bfloat16(o3 - __bfloat162float(h3)));
    }
}

// ---------------------------------------------------------------------------
// launch
// ---------------------------------------------------------------------------
extern "C" void kernel_launch(void* const* d_in, const int* in_sizes, int n_in,
                              void* d_out, int out_size)
{
    const float* x  = (const float*)d_in[0];
    const float* Wq = (const float*)d_in[1];
    const float* bq = (const float*)d_in[2];
    const float* Wk = (const float*)d_in[3];
    const float* bk = (const float*)d_in[4];
    const float* Wv = (const float*)d_in[5];
    const float* bv = (const float*)d_in[6];
    const float* Wo = (const float*)d_in[7];
    const float* bo = (const float*)d_in[8];
    float* out = (float*)d_out;

    float *ct, *st;
    __nv_bfloat16 *qr, *kr, *vhp, *vlp;
    __nv_bfloat16 *xh, *xl, *oh, *ol;
    __nv_bfloat16 *wqkvh, *wqkvl, *woh, *wol;
    cudaGetSymbolAddress((void**)&ct, g_cos);
    cudaGetSymbolAddress((void**)&st, g_sin);
    cudaGetSymbolAddress((void**)&qr, g_qr);
    cudaGetSymbolAddress((void**)&kr, g_kr);
    cudaGetSymbolAddress((void**)&vhp, g_vh);
    cudaGetSymbolAddress((void**)&vlp, g_vl);
    cudaGetSymbolAddress((void**)&xh, g_xh);
    cudaGetSymbolAddress((void**)&xl, g_xl);
    cudaGetSymbolAddress((void**)&oh, g_oh);
    cudaGetSymbolAddress((void**)&ol, g_ol);
    cudaGetSymbolAddress((void**)&wqkvh, g_wqkvh);
    cudaGetSymbolAddress((void**)&wqkvl, g_wqkvl);
    cudaGetSymbolAddress((void**)&woh, g_woh);
    cudaGetSymbolAddress((void**)&wol, g_wol);

    cudaFuncSetAttribute(gemm_qkv_kernel, cudaFuncAttributeMaxDynamicSharedMemorySize, GEMM_SMEM);
    cudaFuncSetAttribute(gemm_out_kernel, cudaFuncAttributeMaxDynamicSharedMemorySize, GEMM_SMEM);
    cudaFuncSetAttribute(attn_mma_kernel, cudaFuncAttributeMaxDynamicSharedMemorySize, ATT_SMEM);

    // prep: weight transposes into packed buffer + x split + rope table
    tsplit_kernel<<<dim3(NE / 32, NE / 32), 256>>>(Wq, wqkvh, wqkvl, NE, NE);
    tsplit_kernel<<<dim3(KVDIM / 32, NE / 32), 256>>>(Wk, wqkvh + (size_t)NE * NE,
                                                      wqkvl + (size_t)NE * NE, NE, KVDIM);
    tsplit_kernel<<<dim3(KVDIM / 32, NE / 32), 256>>>(Wv, wqkvh + (size_t)(NE + KVDIM) * NE,
                                                      wqkvl + (size_t)(NE + KVDIM) * NE, NE, KVDIM);
    tsplit_kernel<<<dim3(NE / 32, NE / 32), 256>>>(Wo, woh, wol, NE, NE);
    split_kernel<<<(MROWS * NE / 8 + 255) / 256, 256>>>(x, xh, xl, MROWS * NE / 8);
    rope_table_kernel<<<(TT * 64 + 255) / 256, 256>>>(ct, st);

    // fused QKV projection (rope + v-split epilogue)
    gemm_qkv_kernel<<<dim3(NQKV / 128, MROWS / 256), 256, GEMM_SMEM>>>(
        xh, xl, wqkvh, wqkvl, bq, bk, bv, ct, st, qr, kr, vhp, vlp);

    // attention (writes split-bf16 oh/ol)
    {
        dim3 grid(TT / 128, NH, BB);
        attn_mma_kernel<<<grid, 256, ATT_SMEM>>>(qr, kr, vhp, vlp, oh, ol);
    }

    // output projection
    gemm_out_kernel<<<dim3(NE / 128, MROWS / 256), 256, GEMM_SMEM>>>(
        oh, ol, woh, wol, bo, out);
}